// round 12
// baseline (speedup 1.0000x reference)
#include <cuda_runtime.h>
#include <cuda_fp16.h>
#include <math.h>
#include <stdint.h>

// B=8, N=128, D=256
#define BN2 1024           // B*N
#define ROWS_E 131072      // B*N*N

// ---------------- scratch (device globals; no allocation allowed) -------------
__device__ __align__(16) __half g_pre1h[67108864]; // [B*N*N,512]: 0..255 fuse, 256..511 fc
__device__ __align__(16) __half g_pre2h[67108864];
__device__ __align__(16) __half g_Wh1[512 * 256];  // fp16 [N][K]
__device__ __align__(16) __half g_Wh2[512 * 256];
__device__ __align__(16) __half g_WhP[1536 * 256];
__device__ __align__(16) __half g_Wh3[256 * 512];
__device__ __align__(16) __half g_Whw[256 * 256];
__device__ __align__(16) __half g_text16[1024 * 256];
__device__ __align__(16) __half g_P16[1024 * 1536]; // [A1|B1|A2|B2|U1|U2]
__device__ __align__(16) __half g_out16[1024 * 256];
__device__ __align__(16) __half g_OC16[1024 * 512]; // [out1|out2]
__device__ float g_out[1024 * 256];
__device__ float g_H[1024 * 256];

// ---------------- helpers ----------------------------------------------------
__device__ __forceinline__ float blockSum256(float v) {
    __shared__ float red[8];
    #pragma unroll
    for (int o = 16; o; o >>= 1) v += __shfl_xor_sync(0xffffffffu, v, o);
    if ((threadIdx.x & 31) == 0) red[threadIdx.x >> 5] = v;
    __syncthreads();
    float s = red[0];
    #pragma unroll
    for (int k = 1; k < 8; k++) s += red[k];
    __syncthreads();
    return s;
}

__device__ __forceinline__ void mma_f16(float* d, const uint32_t* a, const uint32_t* b) {
    asm volatile(
        "mma.sync.aligned.m16n8k16.row.col.f32.f16.f16.f32 "
        "{%0,%1,%2,%3}, {%4,%5,%6,%7}, {%8,%9}, {%0,%1,%2,%3};\n"
        : "+f"(d[0]), "+f"(d[1]), "+f"(d[2]), "+f"(d[3])
        : "r"(a[0]), "r"(a[1]), "r"(a[2]), "r"(a[3]), "r"(b[0]), "r"(b[1]));
}

__device__ __forceinline__ void cp16(uint32_t dst, const void* src) {
    asm volatile("cp.async.cg.shared.global [%0], [%1], 16;\n" :: "r"(dst), "l"(src));
}

__device__ __forceinline__ uint32_t pack_h2(float a, float b) {
    __half2 h = __floats2half2_rn(a, b);
    return *(uint32_t*)&h;
}

__device__ __forceinline__ void ldm_x4(uint32_t* r, uint32_t addr) {
    asm volatile("ldmatrix.sync.aligned.m8n8.x4.shared.b16 {%0,%1,%2,%3}, [%4];"
                 : "=r"(r[0]), "=r"(r[1]), "=r"(r[2]), "=r"(r[3]) : "r"(addr));
}

// ---------------- weight repack (fp16, [N][K]) + text conversion --------------
__global__ void repack_all_h(const float* __restrict__ weight,
                             const float* __restrict__ fuse1_w,
                             const float* __restrict__ fuse2_w,
                             const float* __restrict__ fc3_w,
                             const float* __restrict__ fc1_w0,
                             const float* __restrict__ fc2_w0,
                             const float* __restrict__ text) {
    int n = blockIdx.x;     // 0..255
    int k = threadIdx.x;    // 0..255
    int seg = blockIdx.y;   // 0..12
    const float* src;
    __half* dst;
    switch (seg) {
        case 0:  src = fuse1_w + 256 * 256; dst = g_Wh1;              break;
        case 1:  src = fc1_w0 + 512 * 256;  dst = g_Wh1 + 256 * 256;  break;
        case 2:  src = fuse2_w + 256 * 256; dst = g_Wh2;              break;
        case 3:  src = fc2_w0 + 512 * 256;  dst = g_Wh2 + 256 * 256;  break;
        case 4:  src = fc1_w0;              dst = g_WhP;              break;
        case 5:  src = fc1_w0 + 256 * 256;  dst = g_WhP + 256 * 256;  break;
        case 6:  src = fc2_w0;              dst = g_WhP + 512 * 256;  break;
        case 7:  src = fc2_w0 + 256 * 256;  dst = g_WhP + 768 * 256;  break;
        case 8:  src = fuse1_w;             dst = g_WhP + 1024 * 256; break;
        case 9:  src = fuse2_w;             dst = g_WhP + 1280 * 256; break;
        case 10: src = weight;              dst = g_Whw;              break;
        case 11: // fc3: K = 512
            g_Wh3[n * 512 + k]       = __float2half(fc3_w[k * 256 + n]);
            g_Wh3[n * 512 + k + 256] = __float2half(fc3_w[(k + 256) * 256 + n]);
            return;
        default: // text conversion
            g_text16[n * 1024 + k]       = __float2half(text[n * 1024 + k]);
            g_text16[n * 1024 + 256 + k] = __float2half(text[n * 1024 + 256 + k]);
            g_text16[n * 1024 + 512 + k] = __float2half(text[n * 1024 + 512 + k]);
            g_text16[n * 1024 + 768 + k] = __float2half(text[n * 1024 + 768 + k]);
            return;
    }
    dst[n * 256 + k] = __float2half(src[k * 256 + n]);
}

// ---------------- fp16 tensor GEMM (small shapes): C = A_h @ Wt^T -------------
#define HSTAGE 5120             // halfs per stage per matrix (128*40)
__global__ __launch_bounds__(256, 2) void hgemm(
    const __half* __restrict__ A, const __half* __restrict__ Wt,
    float* __restrict__ C, __half* __restrict__ Ch,
    int M, int N, int K, int doRelu) {
    __shared__ __half As[2][128][40];
    __shared__ __half Bs[2][128][40];
    const int tid = threadIdx.x;
    const int wid = tid >> 5, lane = tid & 31;
    const int g = lane >> 2, qt = lane & 3;
    const int warp_m = wid & 1, warp_n = wid >> 1;
    const int row0 = blockIdx.y * 128;
    const int col0 = blockIdx.x * 128;

    const uint32_t aAddr = (uint32_t)__cvta_generic_to_shared(&As[0][0][0]);
    const uint32_t bAddr = (uint32_t)__cvta_generic_to_shared(&Bs[0][0][0]);
    const int ldr = tid >> 2;          // 0..63
    const int ldc = (tid & 3) * 8;     // 0,8,16,24

    float acc[4][4][4];
    #pragma unroll
    for (int i = 0; i < 4; i++)
        #pragma unroll
        for (int j = 0; j < 4; j++)
            #pragma unroll
            for (int r = 0; r < 4; r++) acc[i][j][r] = 0.f;

    const int KT = K >> 5;

    #pragma unroll
    for (int i = 0; i < 2; i++) {
        int r = ldr + 64 * i;
        cp16(aAddr + (uint32_t)(r * 40 + ldc) * 2, A + (size_t)(row0 + r) * K + ldc);
        cp16(bAddr + (uint32_t)(r * 40 + ldc) * 2, Wt + (size_t)(col0 + r) * K + ldc);
    }
    asm volatile("cp.async.commit_group;\n");

    for (int kt = 0; kt < KT; kt++) {
        if (kt + 1 < KT) {
            int kk = (kt + 1) << 5;
            uint32_t so = (uint32_t)(((kt + 1) & 1) * HSTAGE * 2);
            #pragma unroll
            for (int i = 0; i < 2; i++) {
                int r = ldr + 64 * i;
                cp16(aAddr + so + (uint32_t)(r * 40 + ldc) * 2,
                     A + (size_t)(row0 + r) * K + kk + ldc);
                cp16(bAddr + so + (uint32_t)(r * 40 + ldc) * 2,
                     Wt + (size_t)(col0 + r) * K + kk + ldc);
            }
            asm volatile("cp.async.commit_group;\n");
            asm volatile("cp.async.wait_group 1;\n");
        } else {
            asm volatile("cp.async.wait_group 0;\n");
        }
        __syncthreads();

        const __half* Ac = &As[kt & 1][0][0];
        const __half* Bc = &Bs[kt & 1][0][0];
        #pragma unroll
        for (int ks = 0; ks < 2; ks++) {
            int ko = ks * 16;
            uint32_t af[4][4], bfr[4][2];
            #pragma unroll
            for (int mt = 0; mt < 4; mt++) {
                int R = warp_m * 64 + mt * 16 + g;
                af[mt][0] = *(const uint32_t*)&Ac[R * 40 + ko + 2 * qt];
                af[mt][1] = *(const uint32_t*)&Ac[(R + 8) * 40 + ko + 2 * qt];
                af[mt][2] = *(const uint32_t*)&Ac[R * 40 + ko + 2 * qt + 8];
                af[mt][3] = *(const uint32_t*)&Ac[(R + 8) * 40 + ko + 2 * qt + 8];
            }
            #pragma unroll
            for (int nt = 0; nt < 4; nt++) {
                int Cc = warp_n * 32 + nt * 8 + g;
                bfr[nt][0] = *(const uint32_t*)&Bc[Cc * 40 + ko + 2 * qt];
                bfr[nt][1] = *(const uint32_t*)&Bc[Cc * 40 + ko + 2 * qt + 8];
            }
            #pragma unroll
            for (int mt = 0; mt < 4; mt++)
                #pragma unroll
                for (int nt = 0; nt < 4; nt++)
                    mma_f16(acc[mt][nt], af[mt], bfr[nt]);
        }
        __syncthreads();
    }

    #pragma unroll
    for (int mt = 0; mt < 4; mt++) {
        int R = row0 + warp_m * 64 + mt * 16 + g;
        #pragma unroll
        for (int nt = 0; nt < 4; nt++) {
            int Cc = col0 + warp_n * 32 + nt * 8 + 2 * qt;
            float c0 = acc[mt][nt][0], c1 = acc[mt][nt][1];
            float c2 = acc[mt][nt][2], c3 = acc[mt][nt][3];
            if (doRelu) {
                c0 = fmaxf(c0, 0.f); c1 = fmaxf(c1, 0.f);
                c2 = fmaxf(c2, 0.f); c3 = fmaxf(c3, 0.f);
            }
            if (C) {
                float2 v0 = {c0, c1}, v1 = {c2, c3};
                *(float2*)(C + (size_t)R * N + Cc) = v0;
                *(float2*)(C + (size_t)(R + 8) * N + Cc) = v1;
            }
            if (Ch) {
                *(__half2*)(Ch + (size_t)R * N + Cc) = __floats2half2_rn(c0, c1);
                *(__half2*)(Ch + (size_t)(R + 8) * N + Cc) = __floats2half2_rn(c2, c3);
            }
        }
    }
}

// ---------------- edge GEMM: fp32 A -> in-kernel fp16, ldmatrix fragments -----
// 128x128 tile, BK=32. A: LDG fp32 reg-pipelined, STS as fp16. B: cp.async.
__global__ __launch_bounds__(256, 2) void hgemm_edge(
    const float* __restrict__ A, const __half* __restrict__ Wt,
    __half* __restrict__ Ch, int M, int N, int K) {
    __shared__ __half As[2][128][40];
    __shared__ __half Bs[2][128][40];
    const int tid = threadIdx.x;
    const int wid = tid >> 5, lane = tid & 31;
    const int g = lane >> 2, qt = lane & 3;
    const int warp_m = wid & 1, warp_n = wid >> 1;
    const int row0 = blockIdx.y * 128;
    const int col0 = blockIdx.x * 128;

    const uint32_t aSm = (uint32_t)__cvta_generic_to_shared(&As[0][0][0]);
    const uint32_t bSm = (uint32_t)__cvta_generic_to_shared(&Bs[0][0][0]);
    const int arow = tid >> 1;          // 0..127
    const int acol = (tid & 1) * 16;    // 0 or 16 (floats)
    const int brow = tid >> 2;          // 0..63
    const int bcol = (tid & 3) * 8;     // halfs
    const int lrow = (lane & 7) + 8 * ((lane >> 3) & 1);  // ldmatrix row-in-tile
    const int lcol = (lane >> 4) << 3;                     // 0 or 8

    float acc[4][4][4];
    #pragma unroll
    for (int i = 0; i < 4; i++)
        #pragma unroll
        for (int j = 0; j < 4; j++)
            #pragma unroll
            for (int r = 0; r < 4; r++) acc[i][j][r] = 0.f;

    const int KT = K >> 5;   // 8
    float4 aR[4];

    // prologue: A0 via LDG+cvt+STS, B0 via cp.async
    #pragma unroll
    for (int i = 0; i < 4; i++)
        aR[i] = *(const float4*)(A + (size_t)(row0 + arow) * K + acol + 4 * i);
    #pragma unroll
    for (int i = 0; i < 2; i++)
        cp16(bSm + (uint32_t)((brow + 64 * i) * 40 + bcol) * 2,
             Wt + (size_t)(col0 + brow + 64 * i) * K + bcol);
    asm volatile("cp.async.commit_group;\n");
    #pragma unroll
    for (int i = 0; i < 4; i++) {
        uint2 h;
        h.x = pack_h2(aR[i].x, aR[i].y);
        h.y = pack_h2(aR[i].z, aR[i].w);
        *(uint2*)&As[0][arow][acol + 4 * i] = h;
    }

    for (int kt = 0; kt < KT; kt++) {
        asm volatile("cp.async.wait_group 0;\n");
        __syncthreads();
        const int c = kt & 1, nx = c ^ 1;
        if (kt + 1 < KT) {
            int kk = (kt + 1) << 5;
            #pragma unroll
            for (int i = 0; i < 4; i++)
                aR[i] = *(const float4*)(A + (size_t)(row0 + arow) * K + kk + acol + 4 * i);
            #pragma unroll
            for (int i = 0; i < 2; i++)
                cp16(bSm + (uint32_t)(nx * HSTAGE + (brow + 64 * i) * 40 + bcol) * 2,
                     Wt + (size_t)(col0 + brow + 64 * i) * K + kk + bcol);
            asm volatile("cp.async.commit_group;\n");
        }

        #pragma unroll
        for (int ks = 0; ks < 2; ks++) {
            int ko = ks * 16;
            uint32_t af[4][4], bt[2][4];
            #pragma unroll
            for (int mt = 0; mt < 4; mt++)
                ldm_x4(af[mt], aSm + (uint32_t)((c * HSTAGE +
                    (warp_m * 64 + mt * 16 + lrow) * 40 + ko + lcol) << 1));
            #pragma unroll
            for (int ntp = 0; ntp < 2; ntp++)
                ldm_x4(bt[ntp], bSm + (uint32_t)((c * HSTAGE +
                    (warp_n * 32 + ntp * 16 + lrow) * 40 + ko + lcol) << 1));
            uint32_t bfr[4][2];
            bfr[0][0] = bt[0][0]; bfr[0][1] = bt[0][2];
            bfr[1][0] = bt[0][1]; bfr[1][1] = bt[0][3];
            bfr[2][0] = bt[1][0]; bfr[2][1] = bt[1][2];
            bfr[3][0] = bt[1][1]; bfr[3][1] = bt[1][3];
            #pragma unroll
            for (int mt = 0; mt < 4; mt++)
                #pragma unroll
                for (int nt = 0; nt < 4; nt++)
                    mma_f16(acc[mt][nt], af[mt], bfr[nt]);
        }

        if (kt + 1 < KT) {
            #pragma unroll
            for (int i = 0; i < 4; i++) {
                uint2 h;
                h.x = pack_h2(aR[i].x, aR[i].y);
                h.y = pack_h2(aR[i].z, aR[i].w);
                *(uint2*)&As[nx][arow][acol + 4 * i] = h;
            }
        }
        __syncthreads();
    }

    #pragma unroll
    for (int mt = 0; mt < 4; mt++) {
        int R = row0 + warp_m * 64 + mt * 16 + g;
        #pragma unroll
        for (int nt = 0; nt < 4; nt++) {
            int Cc = col0 + warp_n * 32 + nt * 8 + 2 * qt;
            *(__half2*)(Ch + (size_t)R * N + Cc) =
                __floats2half2_rn(acc[mt][nt][0], acc[mt][nt][1]);
            *(__half2*)(Ch + (size_t)(R + 8) * N + Cc) =
                __floats2half2_rn(acc[mt][nt][2], acc[mt][nt][3]);
        }
    }
}

// ---------------- fused score + aggregate: one block per (b,i) ----------------
__global__ __launch_bounds__(256) void scoreagg_kernel(
    const __half* __restrict__ P,
    const float* __restrict__ adj1, const float* __restrict__ adj2,
    const float* __restrict__ fc1_w1, const float* __restrict__ fc2_w1,
    const float* __restrict__ fc1_b1, const float* __restrict__ fc2_b1,
    __half* __restrict__ OC) {
    int bid = blockIdx.x;            // b*N + i
    int b = bid >> 7;
    int tid = threadIdx.x, wid = tid >> 5, lane = tid & 31;
    __shared__ __half2 PiA[256];
    __shared__ float w1s[128], w2s[128], sred[8];

    const __half* Pi = P + (size_t)bid * 1536;
    float d1 = 0.f, d2 = 0.f;
    if (tid < 128) {
        PiA[tid]       = *(const __half2*)&Pi[2 * tid];          // A1
        PiA[128 + tid] = *(const __half2*)&Pi[512 + 2 * tid];    // A2
        d1 = adj1[bid * 128 + tid];
        d2 = adj2[bid * 128 + tid];
    }
    #pragma unroll
    for (int o = 16; o; o >>= 1) {
        d1 += __shfl_xor_sync(0xffffffffu, d1, o);
        d2 += __shfl_xor_sync(0xffffffffu, d2, o);
    }
    if (tid < 128 && lane == 0) { sred[wid] = d1; sred[4 + wid] = d2; }
    __syncthreads();
    float denom1 = sred[0] + sred[1] + sred[2] + sred[3] + 1.0f;
    float denom2 = sred[4] + sred[5] + sred[6] + sred[7] + 1.0f;
    float bb1 = fc1_b1[0], bb2 = fc2_b1[0];

    // phase 1: scores
    for (int jj = 0; jj < 16; jj++) {
        int j = wid * 16 + jj;
        const __half2* Pj = (const __half2*)(P + (size_t)(b * 128 + j) * 1536);
        const __half2* e1 = (const __half2*)(g_pre1h + ((size_t)bid * 128 + j) * 512 + 256);
        const __half2* e2 = (const __half2*)(g_pre2h + ((size_t)bid * 128 + j) * 512 + 256);
        float s1 = 0.f, s2 = 0.f;
        #pragma unroll
        for (int t = 0; t < 4; t++) {
            int p = lane + 32 * t;
            float2 a1 = __half22float2(PiA[p]);
            float2 a2 = __half22float2(PiA[128 + p]);
            float2 b1v = __half22float2(Pj[128 + p]);  // B1
            float2 b2v = __half22float2(Pj[384 + p]);  // B2
            float2 f1 = __half22float2(e1[p]);
            float2 f2 = __half22float2(e2[p]);
            float2 w1 = *(const float2*)&fc1_w1[2 * p];
            float2 w2 = *(const float2*)&fc2_w1[2 * p];
            s1 = fmaf(fmaxf(a1.x + b1v.x + f1.x, 0.f), w1.x, s1);
            s1 = fmaf(fmaxf(a1.y + b1v.y + f1.y, 0.f), w1.y, s1);
            s2 = fmaf(fmaxf(a2.x + b2v.x + f2.x, 0.f), w2.x, s2);
            s2 = fmaf(fmaxf(a2.y + b2v.y + f2.y, 0.f), w2.y, s2);
        }
        #pragma unroll
        for (int o = 16; o; o >>= 1) {
            s1 += __shfl_xor_sync(0xffffffffu, s1, o);
            s2 += __shfl_xor_sync(0xffffffffu, s2, o);
        }
        if (lane == 0) {
            w1s[j] = adj1[bid * 128 + j] / (1.f + __expf(-(s1 + bb1)));
            w2s[j] = adj2[bid * 128 + j] / (1.f + __expf(-(s2 + bb2)));
        }
    }
    __syncthreads();

    // phase 2: half the threads per matrix, half2-vectorized over d
    int half_id = tid >> 7;          // 0 -> out1, 1 -> out2
    int dt = tid & 127;              // d-pair index
    const __half2* U = (const __half2*)(P + (size_t)(b * 128) * 1536
                                        + (half_id ? 1280 : 1024));
    const __half2* E = (const __half2*)((half_id ? g_pre2h : g_pre1h)
                                        + (size_t)bid * 128 * 512);
    const float* ws = half_id ? w2s : w1s;
    float inv = 1.0f / (half_id ? denom2 : denom1);
    float2 acc = {0.f, 0.f};
    #pragma unroll 4
    for (int j = 0; j < 128; j++) {
        float2 u = __half22float2(U[j * 768 + dt]);
        float2 f = __half22float2(E[j * 256 + dt]);
        float w = ws[j];
        acc.x = fmaf(w, fmaxf(u.x + f.x, 0.f), acc.x);
        acc.y = fmaf(w, fmaxf(u.y + f.y, 0.f), acc.y);
    }
    *(__half2*)&OC[(size_t)bid * 512 + half_id * 256 + 2 * dt] =
        __floats2half2_rn(acc.x * inv, acc.y * inv);
}

// ---------------- relu + residual + bias + layernorm --------------------------
__global__ __launch_bounds__(256) void ln_kernel(
    const float* __restrict__ H, const float* __restrict__ prev,
    const float* __restrict__ bias, const float* __restrict__ gamma,
    const float* __restrict__ beta, float* __restrict__ dst,
    __half* __restrict__ dst16) {
    int row = blockIdx.x, tid = threadIdx.x;
    float v = fmaxf(H[(size_t)row * 256 + tid], 0.f)
              + prev[(size_t)row * 256 + tid] + bias[tid];
    float mean = blockSum256(v) * (1.0f / 256.0f);
    float c = v - mean;
    float var = blockSum256(c * c) * (1.0f / 256.0f);
    float r = c * rsqrtf(var + 1e-5f) * gamma[tid] + beta[tid];
    dst[(size_t)row * 256 + tid] = r;
    dst16[(size_t)row * 256 + tid] = __float2half(r);
}

// ---------------- self-alignment: outss --------------------------------------
__global__ __launch_bounds__(256) void align_kernel(
    const float* __restrict__ text, const float* __restrict__ textmask,
    const float* __restrict__ AL, const float* __restrict__ abias,
    float* __restrict__ outss) {
    int bid = blockIdx.x;    // b*N + i
    int b = bid >> 7;
    int tid = threadIdx.x;
    __shared__ float xi[256], q[256], lg[128], sred[2];
    xi[tid] = text[(size_t)bid * 256 + tid];
    __syncthreads();
    float acc = 0.f;
    #pragma unroll 4
    for (int k = 0; k < 256; k++) acc = fmaf(xi[k], AL[k * 256 + tid], acc);
    q[tid] = acc;
    __syncthreads();

    int w = tid >> 5, lane = tid & 31;
    for (int j = w * 16; j < w * 16 + 16; j++) {
        const float* tj = text + (size_t)(b * 128 + j) * 256;
        float a = 0.f;
        #pragma unroll
        for (int t = 0; t < 8; t++) {
            int d = lane + 32 * t;
            a = fmaf(q[d], tj[d], a);
        }
        #pragma unroll
        for (int o = 16; o; o >>= 1) a += __shfl_xor_sync(0xffffffffu, a, o);
        if (lane == 0)
            lg[j] = a + (1.0f - textmask[b * 128 + j]) * -1e20f;
    }
    __syncthreads();
    if (tid < 32) {
        float m = -3.4e38f;
        for (int k = tid; k < 128; k += 32) m = fmaxf(m, lg[k]);
        #pragma unroll
        for (int o = 16; o; o >>= 1) m = fmaxf(m, __shfl_xor_sync(0xffffffffu, m, o));
        if (tid == 0) sred[0] = m;
    }
    __syncthreads();
    float mx = sred[0];
    if (tid < 128) lg[tid] = __expf(lg[tid] - mx);
    __syncthreads();
    if (tid < 32) {
        float s = 0.f;
        for (int k = tid; k < 128; k += 32) s += lg[k];
        #pragma unroll
        for (int o = 16; o; o >>= 1) s += __shfl_xor_sync(0xffffffffu, s, o);
        if (tid == 0) sred[1] = s;
    }
    __syncthreads();
    float inv = 1.0f / sred[1];
    float a2 = 0.f;
    for (int j = 0; j < 128; j++)
        a2 = fmaf(lg[j], text[(size_t)(b * 128 + j) * 256 + tid], a2);
    outss[(size_t)bid * 256 + tid] = a2 * inv * textmask[bid] + abias[tid];
}

// ---------------- launch ------------------------------------------------------
extern "C" void kernel_launch(void* const* d_in, const int* in_sizes, int n_in,
                              void* d_out, int out_size) {
    const float* text      = (const float*)d_in[0];
    const float* adj1      = (const float*)d_in[1];
    const float* adj2      = (const float*)d_in[2];
    const float* edge1     = (const float*)d_in[3];
    const float* edge2     = (const float*)d_in[4];
    const float* textmask  = (const float*)d_in[5];
    const float* weight    = (const float*)d_in[6];
    const float* bias      = (const float*)d_in[7];
    const float* gamma     = (const float*)d_in[8];
    const float* beta      = (const float*)d_in[9];
    const float* fuse1_w   = (const float*)d_in[10];
    const float* fuse2_w   = (const float*)d_in[11];
    const float* fc3_w     = (const float*)d_in[12];
    const float* fc1_w0    = (const float*)d_in[13];
    const float* fc1_w1    = (const float*)d_in[14];
    const float* fc1_b1    = (const float*)d_in[15];
    const float* fc2_w0    = (const float*)d_in[16];
    const float* fc2_w1    = (const float*)d_in[17];
    const float* fc2_b1    = (const float*)d_in[18];
    const float* align_lin = (const float*)d_in[19];
    const float* align_bias= (const float*)d_in[20];
    float* out = (float*)d_out;

    __half *p_pre1, *p_pre2, *p_Wh1, *p_Wh2, *p_WhP, *p_Wh3,
           *p_Whw, *p_t16, *p_P16, *p_out16, *p_OC16;
    float *p_out, *p_H;
    cudaGetSymbolAddress((void**)&p_pre1,  g_pre1h);
    cudaGetSymbolAddress((void**)&p_pre2,  g_pre2h);
    cudaGetSymbolAddress((void**)&p_Wh1,   g_Wh1);
    cudaGetSymbolAddress((void**)&p_Wh2,   g_Wh2);
    cudaGetSymbolAddress((void**)&p_WhP,   g_WhP);
    cudaGetSymbolAddress((void**)&p_Wh3,   g_Wh3);
    cudaGetSymbolAddress((void**)&p_Whw,   g_Whw);
    cudaGetSymbolAddress((void**)&p_t16,   g_text16);
    cudaGetSymbolAddress((void**)&p_P16,   g_P16);
    cudaGetSymbolAddress((void**)&p_out16, g_out16);
    cudaGetSymbolAddress((void**)&p_OC16,  g_OC16);
    cudaGetSymbolAddress((void**)&p_out,   g_out);
    cudaGetSymbolAddress((void**)&p_H,     g_H);

    // (1) weight repacks + text16 in one launch
    repack_all_h<<<dim3(256, 13), 256>>>(weight, fuse1_w, fuse2_w, fc3_w,
                                         fc1_w0, fc2_w0, text);

    // (2) out = relu(text @ weight), fp32 + fp16
    hgemm<<<dim3(2, 8), 256>>>(p_t16, p_Whw, p_out, p_out16, BN2, 256, 256, 1);

    // (3) independent self-alignment output
    align_kernel<<<BN2, 256>>>(text, textmask, align_lin, align_bias,
                               out + BN2 * 256);

    // (4,5) loop-invariant edge projections: fp32 A, in-kernel cvt, ldmatrix
    hgemm_edge<<<dim3(4, 1024), 256>>>(edge1, p_Wh1, p_pre1, ROWS_E, 512, 256);
    hgemm_edge<<<dim3(4, 1024), 256>>>(edge2, p_Wh2, p_pre2, ROWS_E, 512, 256);

    for (int it = 0; it < 3; it++) {
        // P16 = out @ Wproj
        hgemm<<<dim3(12, 8), 256>>>(p_out16, p_WhP, (float*)0, p_P16,
                                    BN2, 1536, 256, 0);
        scoreagg_kernel<<<BN2, 256>>>(p_P16, adj1, adj2, fc1_w1, fc2_w1,
                                      fc1_b1, fc2_b1, p_OC16);
        // H = [out1|out2] @ fc3_w
        hgemm<<<dim3(2, 8), 256>>>(p_OC16, p_Wh3, p_H, (__half*)0,
                                   BN2, 256, 512, 0);
        float* dst = (it == 2) ? out : p_out;
        ln_kernel<<<BN2, 256>>>(p_H, p_out, bias, gamma, beta, dst, p_out16);
    }
}

// round 13
// speedup vs baseline: 1.4467x; 1.4467x over previous
#include <cuda_runtime.h>
#include <cuda_fp16.h>
#include <math.h>
#include <stdint.h>

// B=8, N=128, D=256
#define BN2 1024           // B*N
#define ROWS_E 131072      // B*N*N

// ---------------- scratch (device globals; no allocation allowed) -------------
__device__ __align__(16) __half g_pre1h[67108864]; // [B*N*N,512]: 0..255 fuse, 256..511 fc
__device__ __align__(16) __half g_pre2h[67108864];
__device__ __align__(16) __half g_Wh1[512 * 256];  // fp16 [N][K]
__device__ __align__(16) __half g_Wh2[512 * 256];
__device__ __align__(16) __half g_WhP[1536 * 256];
__device__ __align__(16) __half g_Wh3[256 * 512];
__device__ __align__(16) __half g_Whw[256 * 256];
__device__ __align__(16) __half g_text16[1024 * 256];
__device__ __align__(16) __half g_P16[1024 * 1536]; // [A1|B1|A2|B2|U1|U2]
__device__ __align__(16) __half g_out16[1024 * 256];
__device__ __align__(16) __half g_OC16[1024 * 512]; // [out1|out2]
__device__ float g_out[1024 * 256];
__device__ float g_H[1024 * 256];

// ---------------- helpers ----------------------------------------------------
__device__ __forceinline__ float blockSum256(float v) {
    __shared__ float red[8];
    #pragma unroll
    for (int o = 16; o; o >>= 1) v += __shfl_xor_sync(0xffffffffu, v, o);
    if ((threadIdx.x & 31) == 0) red[threadIdx.x >> 5] = v;
    __syncthreads();
    float s = red[0];
    #pragma unroll
    for (int k = 1; k < 8; k++) s += red[k];
    __syncthreads();
    return s;
}

__device__ __forceinline__ void mma_f16(float* d, const uint32_t* a, const uint32_t* b) {
    asm volatile(
        "mma.sync.aligned.m16n8k16.row.col.f32.f16.f16.f32 "
        "{%0,%1,%2,%3}, {%4,%5,%6,%7}, {%8,%9}, {%0,%1,%2,%3};\n"
        : "+f"(d[0]), "+f"(d[1]), "+f"(d[2]), "+f"(d[3])
        : "r"(a[0]), "r"(a[1]), "r"(a[2]), "r"(a[3]), "r"(b[0]), "r"(b[1]));
}

__device__ __forceinline__ void cp16(uint32_t dst, const void* src) {
    asm volatile("cp.async.cg.shared.global [%0], [%1], 16;\n" :: "r"(dst), "l"(src));
}

__device__ __forceinline__ uint32_t pack_h2(float a, float b) {
    __half2 h = __floats2half2_rn(a, b);
    return *(uint32_t*)&h;
}

// ---------------- weight repack (fp16, [N][K]) + text conversion --------------
__global__ void repack_all_h(const float* __restrict__ weight,
                             const float* __restrict__ fuse1_w,
                             const float* __restrict__ fuse2_w,
                             const float* __restrict__ fc3_w,
                             const float* __restrict__ fc1_w0,
                             const float* __restrict__ fc2_w0,
                             const float* __restrict__ text) {
    int n = blockIdx.x;     // 0..255
    int k = threadIdx.x;    // 0..255
    int seg = blockIdx.y;   // 0..12
    const float* src;
    __half* dst;
    switch (seg) {
        case 0:  src = fuse1_w + 256 * 256; dst = g_Wh1;              break;
        case 1:  src = fc1_w0 + 512 * 256;  dst = g_Wh1 + 256 * 256;  break;
        case 2:  src = fuse2_w + 256 * 256; dst = g_Wh2;              break;
        case 3:  src = fc2_w0 + 512 * 256;  dst = g_Wh2 + 256 * 256;  break;
        case 4:  src = fc1_w0;              dst = g_WhP;              break;
        case 5:  src = fc1_w0 + 256 * 256;  dst = g_WhP + 256 * 256;  break;
        case 6:  src = fc2_w0;              dst = g_WhP + 512 * 256;  break;
        case 7:  src = fc2_w0 + 256 * 256;  dst = g_WhP + 768 * 256;  break;
        case 8:  src = fuse1_w;             dst = g_WhP + 1024 * 256; break;
        case 9:  src = fuse2_w;             dst = g_WhP + 1280 * 256; break;
        case 10: src = weight;              dst = g_Whw;              break;
        case 11: // fc3: K = 512
            g_Wh3[n * 512 + k]       = __float2half(fc3_w[k * 256 + n]);
            g_Wh3[n * 512 + k + 256] = __float2half(fc3_w[(k + 256) * 256 + n]);
            return;
        default: // text conversion
            g_text16[n * 1024 + k]       = __float2half(text[n * 1024 + k]);
            g_text16[n * 1024 + 256 + k] = __float2half(text[n * 1024 + 256 + k]);
            g_text16[n * 1024 + 512 + k] = __float2half(text[n * 1024 + 512 + k]);
            g_text16[n * 1024 + 768 + k] = __float2half(text[n * 1024 + 768 + k]);
            return;
    }
    dst[n * 256 + k] = __float2half(src[k * 256 + n]);
}

// ---------------- fp16 tensor GEMM (small shapes): C = A_h @ Wt^T -------------
#define HSTAGE 5120             // halfs per stage per matrix (128*40)
__global__ __launch_bounds__(256, 2) void hgemm(
    const __half* __restrict__ A, const __half* __restrict__ Wt,
    float* __restrict__ C, __half* __restrict__ Ch,
    int M, int N, int K, int doRelu) {
    __shared__ __half As[2][128][40];
    __shared__ __half Bs[2][128][40];
    const int tid = threadIdx.x;
    const int wid = tid >> 5, lane = tid & 31;
    const int g = lane >> 2, qt = lane & 3;
    const int warp_m = wid & 1, warp_n = wid >> 1;
    const int row0 = blockIdx.y * 128;
    const int col0 = blockIdx.x * 128;

    const uint32_t aAddr = (uint32_t)__cvta_generic_to_shared(&As[0][0][0]);
    const uint32_t bAddr = (uint32_t)__cvta_generic_to_shared(&Bs[0][0][0]);
    const int ldr = tid >> 2;          // 0..63
    const int ldc = (tid & 3) * 8;     // 0,8,16,24

    float acc[4][4][4];
    #pragma unroll
    for (int i = 0; i < 4; i++)
        #pragma unroll
        for (int j = 0; j < 4; j++)
            #pragma unroll
            for (int r = 0; r < 4; r++) acc[i][j][r] = 0.f;

    const int KT = K >> 5;

    #pragma unroll
    for (int i = 0; i < 2; i++) {
        int r = ldr + 64 * i;
        cp16(aAddr + (uint32_t)(r * 40 + ldc) * 2, A + (size_t)(row0 + r) * K + ldc);
        cp16(bAddr + (uint32_t)(r * 40 + ldc) * 2, Wt + (size_t)(col0 + r) * K + ldc);
    }
    asm volatile("cp.async.commit_group;\n");

    for (int kt = 0; kt < KT; kt++) {
        if (kt + 1 < KT) {
            int kk = (kt + 1) << 5;
            uint32_t so = (uint32_t)(((kt + 1) & 1) * HSTAGE * 2);
            #pragma unroll
            for (int i = 0; i < 2; i++) {
                int r = ldr + 64 * i;
                cp16(aAddr + so + (uint32_t)(r * 40 + ldc) * 2,
                     A + (size_t)(row0 + r) * K + kk + ldc);
                cp16(bAddr + so + (uint32_t)(r * 40 + ldc) * 2,
                     Wt + (size_t)(col0 + r) * K + kk + ldc);
            }
            asm volatile("cp.async.commit_group;\n");
            asm volatile("cp.async.wait_group 1;\n");
        } else {
            asm volatile("cp.async.wait_group 0;\n");
        }
        __syncthreads();

        const __half* Ac = &As[kt & 1][0][0];
        const __half* Bc = &Bs[kt & 1][0][0];
        #pragma unroll
        for (int ks = 0; ks < 2; ks++) {
            int ko = ks * 16;
            uint32_t af[4][4], bfr[4][2];
            #pragma unroll
            for (int mt = 0; mt < 4; mt++) {
                int R = warp_m * 64 + mt * 16 + g;
                af[mt][0] = *(const uint32_t*)&Ac[R * 40 + ko + 2 * qt];
                af[mt][1] = *(const uint32_t*)&Ac[(R + 8) * 40 + ko + 2 * qt];
                af[mt][2] = *(const uint32_t*)&Ac[R * 40 + ko + 2 * qt + 8];
                af[mt][3] = *(const uint32_t*)&Ac[(R + 8) * 40 + ko + 2 * qt + 8];
            }
            #pragma unroll
            for (int nt = 0; nt < 4; nt++) {
                int Cc = warp_n * 32 + nt * 8 + g;
                bfr[nt][0] = *(const uint32_t*)&Bc[Cc * 40 + ko + 2 * qt];
                bfr[nt][1] = *(const uint32_t*)&Bc[Cc * 40 + ko + 2 * qt + 8];
            }
            #pragma unroll
            for (int mt = 0; mt < 4; mt++)
                #pragma unroll
                for (int nt = 0; nt < 4; nt++)
                    mma_f16(acc[mt][nt], af[mt], bfr[nt]);
        }
        __syncthreads();
    }

    #pragma unroll
    for (int mt = 0; mt < 4; mt++) {
        int R = row0 + warp_m * 64 + mt * 16 + g;
        #pragma unroll
        for (int nt = 0; nt < 4; nt++) {
            int Cc = col0 + warp_n * 32 + nt * 8 + 2 * qt;
            float c0 = acc[mt][nt][0], c1 = acc[mt][nt][1];
            float c2 = acc[mt][nt][2], c3 = acc[mt][nt][3];
            if (doRelu) {
                c0 = fmaxf(c0, 0.f); c1 = fmaxf(c1, 0.f);
                c2 = fmaxf(c2, 0.f); c3 = fmaxf(c3, 0.f);
            }
            if (C) {
                float2 v0 = {c0, c1}, v1 = {c2, c3};
                *(float2*)(C + (size_t)R * N + Cc) = v0;
                *(float2*)(C + (size_t)(R + 8) * N + Cc) = v1;
            }
            if (Ch) {
                *(__half2*)(Ch + (size_t)R * N + Cc) = __floats2half2_rn(c0, c1);
                *(__half2*)(Ch + (size_t)(R + 8) * N + Cc) = __floats2half2_rn(c2, c3);
            }
        }
    }
}

// ---------------- fp32-A fp16 GEMM (edge projections) -------------------------
// 128x128 tile, BK=32. A fp32 via cp.async (rounded at fragment load),
// B fp16 via cp.async. Warp grid 4x2 (warp tile 32x64): halves A-fragment
// cross-warp redundancy vs 2x4.
#define ASTG 5120               // floats per A stage (128*40)
#define BSTG 5120               // halfs per B stage (128*40)
__global__ __launch_bounds__(256, 2) void hgemm_f32a(
    const float* __restrict__ A, const __half* __restrict__ Wt,
    __half* __restrict__ Ch, int M, int N, int K) {
    extern __shared__ uint32_t sh[];
    float* As = (float*)sh;                    // [2][128][40] fp32
    __half* Bs = (__half*)(sh + 2 * ASTG);     // [2][128][40] fp16
    const int tid = threadIdx.x;
    const int wid = tid >> 5, lane = tid & 31;
    const int g = lane >> 2, qt = lane & 3;
    const int warp_m = wid >> 1;       // 0..3  (32-row slab)
    const int warp_n = wid & 1;        // 0..1  (64-col slab)
    const int row0 = blockIdx.y * 128;
    const int col0 = blockIdx.x * 128;

    const uint32_t aAddr = (uint32_t)__cvta_generic_to_shared(As);
    const uint32_t bAddr = (uint32_t)__cvta_generic_to_shared(Bs);
    const int ldrA = tid >> 3;         // 0..31
    const int ldcA = (tid & 7) * 4;    // floats
    const int ldrB = tid >> 2;         // 0..63
    const int ldcB = (tid & 3) * 8;    // halfs

    float acc[2][8][4];
    #pragma unroll
    for (int i = 0; i < 2; i++)
        #pragma unroll
        for (int j = 0; j < 8; j++)
            #pragma unroll
            for (int r = 0; r < 4; r++) acc[i][j][r] = 0.f;

    const int KT = K >> 5;

    // prologue
    #pragma unroll
    for (int i = 0; i < 4; i++) {
        int r = ldrA + 32 * i;
        cp16(aAddr + (uint32_t)(r * 40 + ldcA) * 4, A + (size_t)(row0 + r) * K + ldcA);
    }
    #pragma unroll
    for (int i = 0; i < 2; i++) {
        int r = ldrB + 64 * i;
        cp16(bAddr + (uint32_t)(r * 40 + ldcB) * 2, Wt + (size_t)(col0 + r) * K + ldcB);
    }
    asm volatile("cp.async.commit_group;\n");

    for (int kt = 0; kt < KT; kt++) {
        if (kt + 1 < KT) {
            int kk = (kt + 1) << 5;
            uint32_t soA = (uint32_t)(((kt + 1) & 1) * ASTG * 4);
            uint32_t soB = (uint32_t)(((kt + 1) & 1) * BSTG * 2);
            #pragma unroll
            for (int i = 0; i < 4; i++) {
                int r = ldrA + 32 * i;
                cp16(aAddr + soA + (uint32_t)(r * 40 + ldcA) * 4,
                     A + (size_t)(row0 + r) * K + kk + ldcA);
            }
            #pragma unroll
            for (int i = 0; i < 2; i++) {
                int r = ldrB + 64 * i;
                cp16(bAddr + soB + (uint32_t)(r * 40 + ldcB) * 2,
                     Wt + (size_t)(col0 + r) * K + kk + ldcB);
            }
            asm volatile("cp.async.commit_group;\n");
            asm volatile("cp.async.wait_group 1;\n");
        } else {
            asm volatile("cp.async.wait_group 0;\n");
        }
        __syncthreads();

        const float* Ac = As + (kt & 1) * ASTG;
        const __half* Bc = Bs + (kt & 1) * BSTG;
        #pragma unroll
        for (int ks = 0; ks < 2; ks++) {
            int ko = ks * 16;
            uint32_t af[2][4], bfr[8][2];
            #pragma unroll
            for (int mt = 0; mt < 2; mt++) {
                int R = warp_m * 32 + mt * 16 + g;
                float2 v0 = *(const float2*)&Ac[R * 40 + ko + 2 * qt];
                float2 v1 = *(const float2*)&Ac[(R + 8) * 40 + ko + 2 * qt];
                float2 v2 = *(const float2*)&Ac[R * 40 + ko + 2 * qt + 8];
                float2 v3 = *(const float2*)&Ac[(R + 8) * 40 + ko + 2 * qt + 8];
                af[mt][0] = pack_h2(v0.x, v0.y);
                af[mt][1] = pack_h2(v1.x, v1.y);
                af[mt][2] = pack_h2(v2.x, v2.y);
                af[mt][3] = pack_h2(v3.x, v3.y);
            }
            #pragma unroll
            for (int nt = 0; nt < 8; nt++) {
                int Cc = warp_n * 64 + nt * 8 + g;
                bfr[nt][0] = *(const uint32_t*)&Bc[Cc * 40 + ko + 2 * qt];
                bfr[nt][1] = *(const uint32_t*)&Bc[Cc * 40 + ko + 2 * qt + 8];
            }
            #pragma unroll
            for (int mt = 0; mt < 2; mt++)
                #pragma unroll
                for (int nt = 0; nt < 8; nt++)
                    mma_f16(acc[mt][nt], af[mt], bfr[nt]);
        }
        __syncthreads();
    }

    #pragma unroll
    for (int mt = 0; mt < 2; mt++) {
        int R = row0 + warp_m * 32 + mt * 16 + g;
        #pragma unroll
        for (int nt = 0; nt < 8; nt++) {
            int Cc = col0 + warp_n * 64 + nt * 8 + 2 * qt;
            *(__half2*)(Ch + (size_t)R * N + Cc) =
                __floats2half2_rn(acc[mt][nt][0], acc[mt][nt][1]);
            *(__half2*)(Ch + (size_t)(R + 8) * N + Cc) =
                __floats2half2_rn(acc[mt][nt][2], acc[mt][nt][3]);
        }
    }
}

// ---------------- fused score + aggregate: one block per (b,i) ----------------
__global__ __launch_bounds__(256) void scoreagg_kernel(
    const __half* __restrict__ P,
    const float* __restrict__ adj1, const float* __restrict__ adj2,
    const float* __restrict__ fc1_w1, const float* __restrict__ fc2_w1,
    const float* __restrict__ fc1_b1, const float* __restrict__ fc2_b1,
    __half* __restrict__ OC) {
    int bid = blockIdx.x;            // b*N + i
    int b = bid >> 7;
    int tid = threadIdx.x, wid = tid >> 5, lane = tid & 31;
    __shared__ __half2 PiA[256];
    __shared__ float w1s[128], w2s[128], sred[8];

    const __half* Pi = P + (size_t)bid * 1536;
    float d1 = 0.f, d2 = 0.f;
    if (tid < 128) {
        PiA[tid]       = *(const __half2*)&Pi[2 * tid];          // A1
        PiA[128 + tid] = *(const __half2*)&Pi[512 + 2 * tid];    // A2
        d1 = adj1[bid * 128 + tid];
        d2 = adj2[bid * 128 + tid];
    }
    #pragma unroll
    for (int o = 16; o; o >>= 1) {
        d1 += __shfl_xor_sync(0xffffffffu, d1, o);
        d2 += __shfl_xor_sync(0xffffffffu, d2, o);
    }
    if (tid < 128 && lane == 0) { sred[wid] = d1; sred[4 + wid] = d2; }
    __syncthreads();
    float denom1 = sred[0] + sred[1] + sred[2] + sred[3] + 1.0f;
    float denom2 = sred[4] + sred[5] + sred[6] + sred[7] + 1.0f;
    float bb1 = fc1_b1[0], bb2 = fc2_b1[0];

    // phase 1: scores
    for (int jj = 0; jj < 16; jj++) {
        int j = wid * 16 + jj;
        const __half2* Pj = (const __half2*)(P + (size_t)(b * 128 + j) * 1536);
        const __half2* e1 = (const __half2*)(g_pre1h + ((size_t)bid * 128 + j) * 512 + 256);
        const __half2* e2 = (const __half2*)(g_pre2h + ((size_t)bid * 128 + j) * 512 + 256);
        float s1 = 0.f, s2 = 0.f;
        #pragma unroll
        for (int t = 0; t < 4; t++) {
            int p = lane + 32 * t;
            float2 a1 = __half22float2(PiA[p]);
            float2 a2 = __half22float2(PiA[128 + p]);
            float2 b1v = __half22float2(Pj[128 + p]);  // B1
            float2 b2v = __half22float2(Pj[384 + p]);  // B2
            float2 f1 = __half22float2(e1[p]);
            float2 f2 = __half22float2(e2[p]);
            float2 w1 = *(const float2*)&fc1_w1[2 * p];
            float2 w2 = *(const float2*)&fc2_w1[2 * p];
            s1 = fmaf(fmaxf(a1.x + b1v.x + f1.x, 0.f), w1.x, s1);
            s1 = fmaf(fmaxf(a1.y + b1v.y + f1.y, 0.f), w1.y, s1);
            s2 = fmaf(fmaxf(a2.x + b2v.x + f2.x, 0.f), w2.x, s2);
            s2 = fmaf(fmaxf(a2.y + b2v.y + f2.y, 0.f), w2.y, s2);
        }
        #pragma unroll
        for (int o = 16; o; o >>= 1) {
            s1 += __shfl_xor_sync(0xffffffffu, s1, o);
            s2 += __shfl_xor_sync(0xffffffffu, s2, o);
        }
        if (lane == 0) {
            w1s[j] = adj1[bid * 128 + j] / (1.f + __expf(-(s1 + bb1)));
            w2s[j] = adj2[bid * 128 + j] / (1.f + __expf(-(s2 + bb2)));
        }
    }
    __syncthreads();

    // phase 2: aggregation (thread = d)
    float acc1 = 0.f, acc2 = 0.f;
    const __half* Pb = P + (size_t)(b * 128) * 1536;
    const __half* e1 = g_pre1h + (size_t)bid * 128 * 512;
    const __half* e2 = g_pre2h + (size_t)bid * 128 * 512;
    #pragma unroll 4
    for (int j = 0; j < 128; j++) {
        float u1 = __half2float(Pb[j * 1536 + 1024 + tid]);
        float u2 = __half2float(Pb[j * 1536 + 1280 + tid]);
        float f1 = __half2float(e1[j * 512 + tid]);
        float f2 = __half2float(e2[j * 512 + tid]);
        acc1 = fmaf(w1s[j], fmaxf(u1 + f1, 0.f), acc1);
        acc2 = fmaf(w2s[j], fmaxf(u2 + f2, 0.f), acc2);
    }
    OC[(size_t)bid * 512 + tid]       = __float2half(acc1 / denom1);
    OC[(size_t)bid * 512 + 256 + tid] = __float2half(acc2 / denom2);
}

// ---------------- relu + residual + bias + layernorm --------------------------
__global__ __launch_bounds__(256) void ln_kernel(
    const float* __restrict__ H, const float* __restrict__ prev,
    const float* __restrict__ bias, const float* __restrict__ gamma,
    const float* __restrict__ beta, float* __restrict__ dst,
    __half* __restrict__ dst16) {
    int row = blockIdx.x, tid = threadIdx.x;
    float v = fmaxf(H[(size_t)row * 256 + tid], 0.f)
              + prev[(size_t)row * 256 + tid] + bias[tid];
    float mean = blockSum256(v) * (1.0f / 256.0f);
    float c = v - mean;
    float var = blockSum256(c * c) * (1.0f / 256.0f);
    float r = c * rsqrtf(var + 1e-5f) * gamma[tid] + beta[tid];
    dst[(size_t)row * 256 + tid] = r;
    dst16[(size_t)row * 256 + tid] = __float2half(r);
}

// ---------------- self-alignment: outss --------------------------------------
__global__ __launch_bounds__(256) void align_kernel(
    const float* __restrict__ text, const float* __restrict__ textmask,
    const float* __restrict__ AL, const float* __restrict__ abias,
    float* __restrict__ outss) {
    int bid = blockIdx.x;    // b*N + i
    int b = bid >> 7;
    int tid = threadIdx.x;
    __shared__ float xi[256], q[256], lg[128], sred[2];
    xi[tid] = text[(size_t)bid * 256 + tid];
    __syncthreads();
    float acc = 0.f;
    #pragma unroll 4
    for (int k = 0; k < 256; k++) acc = fmaf(xi[k], AL[k * 256 + tid], acc);
    q[tid] = acc;
    __syncthreads();

    int w = tid >> 5, lane = tid & 31;
    for (int j = w * 16; j < w * 16 + 16; j++) {
        const float* tj = text + (size_t)(b * 128 + j) * 256;
        float a = 0.f;
        #pragma unroll
        for (int t = 0; t < 8; t++) {
            int d = lane + 32 * t;
            a = fmaf(q[d], tj[d], a);
        }
        #pragma unroll
        for (int o = 16; o; o >>= 1) a += __shfl_xor_sync(0xffffffffu, a, o);
        if (lane == 0)
            lg[j] = a + (1.0f - textmask[b * 128 + j]) * -1e20f;
    }
    __syncthreads();
    if (tid < 32) {
        float m = -3.4e38f;
        for (int k = tid; k < 128; k += 32) m = fmaxf(m, lg[k]);
        #pragma unroll
        for (int o = 16; o; o >>= 1) m = fmaxf(m, __shfl_xor_sync(0xffffffffu, m, o));
        if (tid == 0) sred[0] = m;
    }
    __syncthreads();
    float mx = sred[0];
    if (tid < 128) lg[tid] = __expf(lg[tid] - mx);
    __syncthreads();
    if (tid < 32) {
        float s = 0.f;
        for (int k = tid; k < 128; k += 32) s += lg[k];
        #pragma unroll
        for (int o = 16; o; o >>= 1) s += __shfl_xor_sync(0xffffffffu, s, o);
        if (tid == 0) sred[1] = s;
    }
    __syncthreads();
    float inv = 1.0f / sred[1];
    float a2 = 0.f;
    for (int j = 0; j < 128; j++)
        a2 = fmaf(lg[j], text[(size_t)(b * 128 + j) * 256 + tid], a2);
    outss[(size_t)bid * 256 + tid] = a2 * inv * textmask[bid] + abias[tid];
}

// ---------------- launch ------------------------------------------------------
#define F32A_SMEM 61440   // 2*(128*40*4) + 2*(128*40*2)

extern "C" void kernel_launch(void* const* d_in, const int* in_sizes, int n_in,
                              void* d_out, int out_size) {
    const float* text      = (const float*)d_in[0];
    const float* adj1      = (const float*)d_in[1];
    const float* adj2      = (const float*)d_in[2];
    const float* edge1     = (const float*)d_in[3];
    const float* edge2     = (const float*)d_in[4];
    const float* textmask  = (const float*)d_in[5];
    const float* weight    = (const float*)d_in[6];
    const float* bias      = (const float*)d_in[7];
    const float* gamma     = (const float*)d_in[8];
    const float* beta      = (const float*)d_in[9];
    const float* fuse1_w   = (const float*)d_in[10];
    const float* fuse2_w   = (const float*)d_in[11];
    const float* fc3_w     = (const float*)d_in[12];
    const float* fc1_w0    = (const float*)d_in[13];
    const float* fc1_w1    = (const float*)d_in[14];
    const float* fc1_b1    = (const float*)d_in[15];
    const float* fc2_w0    = (const float*)d_in[16];
    const float* fc2_w1    = (const float*)d_in[17];
    const float* fc2_b1    = (const float*)d_in[18];
    const float* align_lin = (const float*)d_in[19];
    const float* align_bias= (const float*)d_in[20];
    float* out = (float*)d_out;

    static int attr_done = 0;
    if (!attr_done) {
        cudaFuncSetAttribute(hgemm_f32a,
                             cudaFuncAttributeMaxDynamicSharedMemorySize,
                             F32A_SMEM);
        attr_done = 1;
    }

    __half *p_pre1, *p_pre2, *p_Wh1, *p_Wh2, *p_WhP, *p_Wh3,
           *p_Whw, *p_t16, *p_P16, *p_out16, *p_OC16;
    float *p_out, *p_H;
    cudaGetSymbolAddress((void**)&p_pre1,  g_pre1h);
    cudaGetSymbolAddress((void**)&p_pre2,  g_pre2h);
    cudaGetSymbolAddress((void**)&p_Wh1,   g_Wh1);
    cudaGetSymbolAddress((void**)&p_Wh2,   g_Wh2);
    cudaGetSymbolAddress((void**)&p_WhP,   g_WhP);
    cudaGetSymbolAddress((void**)&p_Wh3,   g_Wh3);
    cudaGetSymbolAddress((void**)&p_Whw,   g_Whw);
    cudaGetSymbolAddress((void**)&p_t16,   g_text16);
    cudaGetSymbolAddress((void**)&p_P16,   g_P16);
    cudaGetSymbolAddress((void**)&p_out16, g_out16);
    cudaGetSymbolAddress((void**)&p_OC16,  g_OC16);
    cudaGetSymbolAddress((void**)&p_out,   g_out);
    cudaGetSymbolAddress((void**)&p_H,     g_H);

    // (1) weight repacks + text16 in one launch
    repack_all_h<<<dim3(256, 13), 256>>>(weight, fuse1_w, fuse2_w, fc3_w,
                                         fc1_w0, fc2_w0, text);

    // (2) out = relu(text @ weight), fp32 + fp16
    hgemm<<<dim3(2, 8), 256>>>(p_t16, p_Whw, p_out, p_out16, BN2, 256, 256, 1);

    // (3) independent self-alignment output
    align_kernel<<<BN2, 256>>>(text, textmask, align_lin, align_bias,
                               out + BN2 * 256);

    // (4,5) loop-invariant edge projections, fp32 A + in-kernel convert
    hgemm_f32a<<<dim3(4, 1024), 256, F32A_SMEM>>>(edge1, p_Wh1, p_pre1,
                                                  ROWS_E, 512, 256);
    hgemm_f32a<<<dim3(4, 1024), 256, F32A_SMEM>>>(edge2, p_Wh2, p_pre2,
                                                  ROWS_E, 512, 256);

    for (int it = 0; it < 3; it++) {
        // P16 = out @ Wproj
        hgemm<<<dim3(12, 8), 256>>>(p_out16, p_WhP, (float*)0, p_P16,
                                    BN2, 1536, 256, 0);
        scoreagg_kernel<<<BN2, 256>>>(p_P16, adj1, adj2, fc1_w1, fc2_w1,
                                      fc1_b1, fc2_b1, p_OC16);
        // H = [out1|out2] @ fc3_w
        hgemm<<<dim3(2, 8), 256>>>(p_OC16, p_Wh3, p_H, (__half*)0,
                                   BN2, 256, 512, 0);
        float* dst = (it == 2) ? out : p_out;
        ln_kernel<<<BN2, 256>>>(p_H, p_out, bias, gamma, beta, dst, p_out16);
    }
}

// round 14
// speedup vs baseline: 1.4553x; 1.0059x over previous
#include <cuda_runtime.h>
#include <cuda_fp16.h>
#include <math.h>
#include <stdint.h>

// B=8, N=128, D=256
#define BN2 1024           // B*N
#define ROWS_E 131072      // B*N*N

// ---------------- scratch (device globals; no allocation allowed) -------------
__device__ __align__(16) __half g_pre1h[67108864]; // [B*N*N,512]: 0..255 fuse, 256..511 fc
__device__ __align__(16) __half g_pre2h[67108864];
__device__ __align__(16) __half g_Wh1[512 * 256];  // fp16 [N][K]
__device__ __align__(16) __half g_Wh2[512 * 256];
__device__ __align__(16) __half g_WhP[1536 * 256];
__device__ __align__(16) __half g_Wh3[256 * 512];
__device__ __align__(16) __half g_Whw[256 * 256];
__device__ __align__(16) __half g_text16[1024 * 256];
__device__ __align__(16) __half g_P16[1024 * 1536]; // [A1|B1|A2|B2|U1|U2]
__device__ __align__(16) __half g_out16[1024 * 256];
__device__ __align__(16) __half g_OC16[1024 * 512]; // [out1|out2]
__device__ float g_out[1024 * 256];
__device__ float g_H[1024 * 256];

// ---------------- helpers ----------------------------------------------------
__device__ __forceinline__ float blockSum256(float v) {
    __shared__ float red[8];
    #pragma unroll
    for (int o = 16; o; o >>= 1) v += __shfl_xor_sync(0xffffffffu, v, o);
    if ((threadIdx.x & 31) == 0) red[threadIdx.x >> 5] = v;
    __syncthreads();
    float s = red[0];
    #pragma unroll
    for (int k = 1; k < 8; k++) s += red[k];
    __syncthreads();
    return s;
}

__device__ __forceinline__ void mma_f16(float* d, const uint32_t* a, const uint32_t* b) {
    asm volatile(
        "mma.sync.aligned.m16n8k16.row.col.f32.f16.f16.f32 "
        "{%0,%1,%2,%3}, {%4,%5,%6,%7}, {%8,%9}, {%0,%1,%2,%3};\n"
        : "+f"(d[0]), "+f"(d[1]), "+f"(d[2]), "+f"(d[3])
        : "r"(a[0]), "r"(a[1]), "r"(a[2]), "r"(a[3]), "r"(b[0]), "r"(b[1]));
}

__device__ __forceinline__ void cp16(uint32_t dst, const void* src) {
    asm volatile("cp.async.cg.shared.global [%0], [%1], 16;\n" :: "r"(dst), "l"(src));
}

__device__ __forceinline__ uint32_t pack_h2(float a, float b) {
    __half2 h = __floats2half2_rn(a, b);
    return *(uint32_t*)&h;
}

// ---------------- weight repack (fp16, [N][K]) + text conversion --------------
__global__ void repack_all_h(const float* __restrict__ weight,
                             const float* __restrict__ fuse1_w,
                             const float* __restrict__ fuse2_w,
                             const float* __restrict__ fc3_w,
                             const float* __restrict__ fc1_w0,
                             const float* __restrict__ fc2_w0,
                             const float* __restrict__ text) {
    int n = blockIdx.x;     // 0..255
    int k = threadIdx.x;    // 0..255
    int seg = blockIdx.y;   // 0..12
    const float* src;
    __half* dst;
    switch (seg) {
        case 0:  src = fuse1_w + 256 * 256; dst = g_Wh1;              break;
        case 1:  src = fc1_w0 + 512 * 256;  dst = g_Wh1 + 256 * 256;  break;
        case 2:  src = fuse2_w + 256 * 256; dst = g_Wh2;              break;
        case 3:  src = fc2_w0 + 512 * 256;  dst = g_Wh2 + 256 * 256;  break;
        case 4:  src = fc1_w0;              dst = g_WhP;              break;
        case 5:  src = fc1_w0 + 256 * 256;  dst = g_WhP + 256 * 256;  break;
        case 6:  src = fc2_w0;              dst = g_WhP + 512 * 256;  break;
        case 7:  src = fc2_w0 + 256 * 256;  dst = g_WhP + 768 * 256;  break;
        case 8:  src = fuse1_w;             dst = g_WhP + 1024 * 256; break;
        case 9:  src = fuse2_w;             dst = g_WhP + 1280 * 256; break;
        case 10: src = weight;              dst = g_Whw;              break;
        case 11: // fc3: K = 512
            g_Wh3[n * 512 + k]       = __float2half(fc3_w[k * 256 + n]);
            g_Wh3[n * 512 + k + 256] = __float2half(fc3_w[(k + 256) * 256 + n]);
            return;
        default: // text conversion
            g_text16[n * 1024 + k]       = __float2half(text[n * 1024 + k]);
            g_text16[n * 1024 + 256 + k] = __float2half(text[n * 1024 + 256 + k]);
            g_text16[n * 1024 + 512 + k] = __float2half(text[n * 1024 + 512 + k]);
            g_text16[n * 1024 + 768 + k] = __float2half(text[n * 1024 + 768 + k]);
            return;
    }
    dst[n * 256 + k] = __float2half(src[k * 256 + n]);
}

// ---------------- fp16 tensor GEMM (small shapes): C = A_h @ Wt^T -------------
#define HSTAGE 5120             // halfs per stage per matrix (128*40)
__global__ __launch_bounds__(256, 2) void hgemm(
    const __half* __restrict__ A, const __half* __restrict__ Wt,
    float* __restrict__ C, __half* __restrict__ Ch,
    int M, int N, int K, int doRelu) {
    __shared__ __half As[2][128][40];
    __shared__ __half Bs[2][128][40];
    const int tid = threadIdx.x;
    const int wid = tid >> 5, lane = tid & 31;
    const int g = lane >> 2, qt = lane & 3;
    const int warp_m = wid & 1, warp_n = wid >> 1;
    const int row0 = blockIdx.y * 128;
    const int col0 = blockIdx.x * 128;

    const uint32_t aAddr = (uint32_t)__cvta_generic_to_shared(&As[0][0][0]);
    const uint32_t bAddr = (uint32_t)__cvta_generic_to_shared(&Bs[0][0][0]);
    const int ldr = tid >> 2;          // 0..63
    const int ldc = (tid & 3) * 8;     // 0,8,16,24

    float acc[4][4][4];
    #pragma unroll
    for (int i = 0; i < 4; i++)
        #pragma unroll
        for (int j = 0; j < 4; j++)
            #pragma unroll
            for (int r = 0; r < 4; r++) acc[i][j][r] = 0.f;

    const int KT = K >> 5;

    #pragma unroll
    for (int i = 0; i < 2; i++) {
        int r = ldr + 64 * i;
        cp16(aAddr + (uint32_t)(r * 40 + ldc) * 2, A + (size_t)(row0 + r) * K + ldc);
        cp16(bAddr + (uint32_t)(r * 40 + ldc) * 2, Wt + (size_t)(col0 + r) * K + ldc);
    }
    asm volatile("cp.async.commit_group;\n");

    for (int kt = 0; kt < KT; kt++) {
        if (kt + 1 < KT) {
            int kk = (kt + 1) << 5;
            uint32_t so = (uint32_t)(((kt + 1) & 1) * HSTAGE * 2);
            #pragma unroll
            for (int i = 0; i < 2; i++) {
                int r = ldr + 64 * i;
                cp16(aAddr + so + (uint32_t)(r * 40 + ldc) * 2,
                     A + (size_t)(row0 + r) * K + kk + ldc);
                cp16(bAddr + so + (uint32_t)(r * 40 + ldc) * 2,
                     Wt + (size_t)(col0 + r) * K + kk + ldc);
            }
            asm volatile("cp.async.commit_group;\n");
            asm volatile("cp.async.wait_group 1;\n");
        } else {
            asm volatile("cp.async.wait_group 0;\n");
        }
        __syncthreads();

        const __half* Ac = &As[kt & 1][0][0];
        const __half* Bc = &Bs[kt & 1][0][0];
        #pragma unroll
        for (int ks = 0; ks < 2; ks++) {
            int ko = ks * 16;
            uint32_t af[4][4], bfr[4][2];
            #pragma unroll
            for (int mt = 0; mt < 4; mt++) {
                int R = warp_m * 64 + mt * 16 + g;
                af[mt][0] = *(const uint32_t*)&Ac[R * 40 + ko + 2 * qt];
                af[mt][1] = *(const uint32_t*)&Ac[(R + 8) * 40 + ko + 2 * qt];
                af[mt][2] = *(const uint32_t*)&Ac[R * 40 + ko + 2 * qt + 8];
                af[mt][3] = *(const uint32_t*)&Ac[(R + 8) * 40 + ko + 2 * qt + 8];
            }
            #pragma unroll
            for (int nt = 0; nt < 4; nt++) {
                int Cc = warp_n * 32 + nt * 8 + g;
                bfr[nt][0] = *(const uint32_t*)&Bc[Cc * 40 + ko + 2 * qt];
                bfr[nt][1] = *(const uint32_t*)&Bc[Cc * 40 + ko + 2 * qt + 8];
            }
            #pragma unroll
            for (int mt = 0; mt < 4; mt++)
                #pragma unroll
                for (int nt = 0; nt < 4; nt++)
                    mma_f16(acc[mt][nt], af[mt], bfr[nt]);
        }
        __syncthreads();
    }

    #pragma unroll
    for (int mt = 0; mt < 4; mt++) {
        int R = row0 + warp_m * 64 + mt * 16 + g;
        #pragma unroll
        for (int nt = 0; nt < 4; nt++) {
            int Cc = col0 + warp_n * 32 + nt * 8 + 2 * qt;
            float c0 = acc[mt][nt][0], c1 = acc[mt][nt][1];
            float c2 = acc[mt][nt][2], c3 = acc[mt][nt][3];
            if (doRelu) {
                c0 = fmaxf(c0, 0.f); c1 = fmaxf(c1, 0.f);
                c2 = fmaxf(c2, 0.f); c3 = fmaxf(c3, 0.f);
            }
            if (C) {
                float2 v0 = {c0, c1}, v1 = {c2, c3};
                *(float2*)(C + (size_t)R * N + Cc) = v0;
                *(float2*)(C + (size_t)(R + 8) * N + Cc) = v1;
            }
            if (Ch) {
                *(__half2*)(Ch + (size_t)R * N + Cc) = __floats2half2_rn(c0, c1);
                *(__half2*)(Ch + (size_t)(R + 8) * N + Cc) = __floats2half2_rn(c2, c3);
            }
        }
    }
}

// ---------------- fp32-A fp16 GEMM (edge projections), 3-stage pipeline -------
// 128x128 tile, BK=32, warp grid 4x2 (warp tile 32x64). A fp32 via cp.async
// (rounded at fragment load), B fp16 via cp.async. Prefetch distance 2.
#define ASTG 5120               // floats per A stage (128*40)
#define BSTG 5120               // halfs per B stage (128*40)
__global__ __launch_bounds__(256, 2) void hgemm_f32a(
    const float* __restrict__ A, const __half* __restrict__ Wt,
    __half* __restrict__ Ch, int M, int N, int K) {
    extern __shared__ uint32_t sh[];
    float* As = (float*)sh;                    // [3][128][40] fp32
    __half* Bs = (__half*)(sh + 3 * ASTG);     // [3][128][40] fp16
    const int tid = threadIdx.x;
    const int wid = tid >> 5, lane = tid & 31;
    const int g = lane >> 2, qt = lane & 3;
    const int warp_m = wid >> 1;       // 0..3  (32-row slab)
    const int warp_n = wid & 1;        // 0..1  (64-col slab)
    const int row0 = blockIdx.y * 128;
    const int col0 = blockIdx.x * 128;

    const uint32_t aAddr = (uint32_t)__cvta_generic_to_shared(As);
    const uint32_t bAddr = (uint32_t)__cvta_generic_to_shared(Bs);
    const int ldrA = tid >> 3;         // 0..31
    const int ldcA = (tid & 7) * 4;    // floats
    const int ldrB = tid >> 2;         // 0..63
    const int ldcB = (tid & 3) * 8;    // halfs

    float acc[2][8][4];
    #pragma unroll
    for (int i = 0; i < 2; i++)
        #pragma unroll
        for (int j = 0; j < 8; j++)
            #pragma unroll
            for (int r = 0; r < 4; r++) acc[i][j][r] = 0.f;

    const int KT = K >> 5;   // 8

    // prologue: fill stages 0 and 1
    #pragma unroll
    for (int s = 0; s < 2; s++) {
        int kk = s << 5;
        uint32_t soA = (uint32_t)(s * ASTG * 4);
        uint32_t soB = (uint32_t)(s * BSTG * 2);
        #pragma unroll
        for (int i = 0; i < 4; i++) {
            int r = ldrA + 32 * i;
            cp16(aAddr + soA + (uint32_t)(r * 40 + ldcA) * 4,
                 A + (size_t)(row0 + r) * K + kk + ldcA);
        }
        #pragma unroll
        for (int i = 0; i < 2; i++) {
            int r = ldrB + 64 * i;
            cp16(bAddr + soB + (uint32_t)(r * 40 + ldcB) * 2,
                 Wt + (size_t)(col0 + r) * K + kk + ldcB);
        }
        asm volatile("cp.async.commit_group;\n");
    }

    for (int kt = 0; kt < KT; kt++) {
        if (kt + 2 < KT) {
            int kk = (kt + 2) << 5;
            int st = (kt + 2) % 3;
            uint32_t soA = (uint32_t)(st * ASTG * 4);
            uint32_t soB = (uint32_t)(st * BSTG * 2);
            #pragma unroll
            for (int i = 0; i < 4; i++) {
                int r = ldrA + 32 * i;
                cp16(aAddr + soA + (uint32_t)(r * 40 + ldcA) * 4,
                     A + (size_t)(row0 + r) * K + kk + ldcA);
            }
            #pragma unroll
            for (int i = 0; i < 2; i++) {
                int r = ldrB + 64 * i;
                cp16(bAddr + soB + (uint32_t)(r * 40 + ldcB) * 2,
                     Wt + (size_t)(col0 + r) * K + kk + ldcB);
            }
            asm volatile("cp.async.commit_group;\n");
            asm volatile("cp.async.wait_group 2;\n");
        } else if (kt + 1 < KT) {
            asm volatile("cp.async.wait_group 1;\n");
        } else {
            asm volatile("cp.async.wait_group 0;\n");
        }
        __syncthreads();

        const int st = kt % 3;
        const float* Ac = As + st * ASTG;
        const __half* Bc = Bs + st * BSTG;
        #pragma unroll
        for (int ks = 0; ks < 2; ks++) {
            int ko = ks * 16;
            uint32_t af[2][4], bfr[8][2];
            #pragma unroll
            for (int mt = 0; mt < 2; mt++) {
                int R = warp_m * 32 + mt * 16 + g;
                float2 v0 = *(const float2*)&Ac[R * 40 + ko + 2 * qt];
                float2 v1 = *(const float2*)&Ac[(R + 8) * 40 + ko + 2 * qt];
                float2 v2 = *(const float2*)&Ac[R * 40 + ko + 2 * qt + 8];
                float2 v3 = *(const float2*)&Ac[(R + 8) * 40 + ko + 2 * qt + 8];
                af[mt][0] = pack_h2(v0.x, v0.y);
                af[mt][1] = pack_h2(v1.x, v1.y);
                af[mt][2] = pack_h2(v2.x, v2.y);
                af[mt][3] = pack_h2(v3.x, v3.y);
            }
            #pragma unroll
            for (int nt = 0; nt < 8; nt++) {
                int Cc = warp_n * 64 + nt * 8 + g;
                bfr[nt][0] = *(const uint32_t*)&Bc[Cc * 40 + ko + 2 * qt];
                bfr[nt][1] = *(const uint32_t*)&Bc[Cc * 40 + ko + 2 * qt + 8];
            }
            #pragma unroll
            for (int mt = 0; mt < 2; mt++)
                #pragma unroll
                for (int nt = 0; nt < 8; nt++)
                    mma_f16(acc[mt][nt], af[mt], bfr[nt]);
        }
        __syncthreads();
    }

    #pragma unroll
    for (int mt = 0; mt < 2; mt++) {
        int R = row0 + warp_m * 32 + mt * 16 + g;
        #pragma unroll
        for (int nt = 0; nt < 8; nt++) {
            int Cc = col0 + warp_n * 64 + nt * 8 + 2 * qt;
            *(__half2*)(Ch + (size_t)R * N + Cc) =
                __floats2half2_rn(acc[mt][nt][0], acc[mt][nt][1]);
            *(__half2*)(Ch + (size_t)(R + 8) * N + Cc) =
                __floats2half2_rn(acc[mt][nt][2], acc[mt][nt][3]);
        }
    }
}

// ---------------- fused score + aggregate: one block per (b,i) ----------------
__global__ __launch_bounds__(256) void scoreagg_kernel(
    const __half* __restrict__ P,
    const float* __restrict__ adj1, const float* __restrict__ adj2,
    const float* __restrict__ fc1_w1, const float* __restrict__ fc2_w1,
    const float* __restrict__ fc1_b1, const float* __restrict__ fc2_b1,
    __half* __restrict__ OC) {
    int bid = blockIdx.x;            // b*N + i
    int b = bid >> 7;
    int tid = threadIdx.x, wid = tid >> 5, lane = tid & 31;
    __shared__ __half2 PiA[256];
    __shared__ float w1s[128], w2s[128], sred[8];

    const __half* Pi = P + (size_t)bid * 1536;
    float d1 = 0.f, d2 = 0.f;
    if (tid < 128) {
        PiA[tid]       = *(const __half2*)&Pi[2 * tid];          // A1
        PiA[128 + tid] = *(const __half2*)&Pi[512 + 2 * tid];    // A2
        d1 = adj1[bid * 128 + tid];
        d2 = adj2[bid * 128 + tid];
    }
    #pragma unroll
    for (int o = 16; o; o >>= 1) {
        d1 += __shfl_xor_sync(0xffffffffu, d1, o);
        d2 += __shfl_xor_sync(0xffffffffu, d2, o);
    }
    if (tid < 128 && lane == 0) { sred[wid] = d1; sred[4 + wid] = d2; }
    __syncthreads();
    float denom1 = sred[0] + sred[1] + sred[2] + sred[3] + 1.0f;
    float denom2 = sred[4] + sred[5] + sred[6] + sred[7] + 1.0f;
    float bb1 = fc1_b1[0], bb2 = fc2_b1[0];

    // phase 1: scores
    for (int jj = 0; jj < 16; jj++) {
        int j = wid * 16 + jj;
        const __half2* Pj = (const __half2*)(P + (size_t)(b * 128 + j) * 1536);
        const __half2* e1 = (const __half2*)(g_pre1h + ((size_t)bid * 128 + j) * 512 + 256);
        const __half2* e2 = (const __half2*)(g_pre2h + ((size_t)bid * 128 + j) * 512 + 256);
        float s1 = 0.f, s2 = 0.f;
        #pragma unroll
        for (int t = 0; t < 4; t++) {
            int p = lane + 32 * t;
            float2 a1 = __half22float2(PiA[p]);
            float2 a2 = __half22float2(PiA[128 + p]);
            float2 b1v = __half22float2(Pj[128 + p]);  // B1
            float2 b2v = __half22float2(Pj[384 + p]);  // B2
            float2 f1 = __half22float2(e1[p]);
            float2 f2 = __half22float2(e2[p]);
            float2 w1 = *(const float2*)&fc1_w1[2 * p];
            float2 w2 = *(const float2*)&fc2_w1[2 * p];
            s1 = fmaf(fmaxf(a1.x + b1v.x + f1.x, 0.f), w1.x, s1);
            s1 = fmaf(fmaxf(a1.y + b1v.y + f1.y, 0.f), w1.y, s1);
            s2 = fmaf(fmaxf(a2.x + b2v.x + f2.x, 0.f), w2.x, s2);
            s2 = fmaf(fmaxf(a2.y + b2v.y + f2.y, 0.f), w2.y, s2);
        }
        #pragma unroll
        for (int o = 16; o; o >>= 1) {
            s1 += __shfl_xor_sync(0xffffffffu, s1, o);
            s2 += __shfl_xor_sync(0xffffffffu, s2, o);
        }
        if (lane == 0) {
            w1s[j] = adj1[bid * 128 + j] / (1.f + __expf(-(s1 + bb1)));
            w2s[j] = adj2[bid * 128 + j] / (1.f + __expf(-(s2 + bb2)));
        }
    }
    __syncthreads();

    // phase 2: aggregation (thread = d)
    float acc1 = 0.f, acc2 = 0.f;
    const __half* Pb = P + (size_t)(b * 128) * 1536;
    const __half* e1 = g_pre1h + (size_t)bid * 128 * 512;
    const __half* e2 = g_pre2h + (size_t)bid * 128 * 512;
    #pragma unroll 4
    for (int j = 0; j < 128; j++) {
        float u1 = __half2float(Pb[j * 1536 + 1024 + tid]);
        float u2 = __half2float(Pb[j * 1536 + 1280 + tid]);
        float f1 = __half2float(e1[j * 512 + tid]);
        float f2 = __half2float(e2[j * 512 + tid]);
        acc1 = fmaf(w1s[j], fmaxf(u1 + f1, 0.f), acc1);
        acc2 = fmaf(w2s[j], fmaxf(u2 + f2, 0.f), acc2);
    }
    OC[(size_t)bid * 512 + tid]       = __float2half(acc1 / denom1);
    OC[(size_t)bid * 512 + 256 + tid] = __float2half(acc2 / denom2);
}

// ---------------- relu + residual + bias + layernorm --------------------------
__global__ __launch_bounds__(256) void ln_kernel(
    const float* __restrict__ H, const float* __restrict__ prev,
    const float* __restrict__ bias, const float* __restrict__ gamma,
    const float* __restrict__ beta, float* __restrict__ dst,
    __half* __restrict__ dst16) {
    int row = blockIdx.x, tid = threadIdx.x;
    float v = fmaxf(H[(size_t)row * 256 + tid], 0.f)
              + prev[(size_t)row * 256 + tid] + bias[tid];
    float mean = blockSum256(v) * (1.0f / 256.0f);
    float c = v - mean;
    float var = blockSum256(c * c) * (1.0f / 256.0f);
    float r = c * rsqrtf(var + 1e-5f) * gamma[tid] + beta[tid];
    dst[(size_t)row * 256 + tid] = r;
    dst16[(size_t)row * 256 + tid] = __float2half(r);
}

// ---------------- self-alignment: outss --------------------------------------
__global__ __launch_bounds__(256) void align_kernel(
    const float* __restrict__ text, const float* __restrict__ textmask,
    const float* __restrict__ AL, const float* __restrict__ abias,
    float* __restrict__ outss) {
    int bid = blockIdx.x;    // b*N + i
    int b = bid >> 7;
    int tid = threadIdx.x;
    __shared__ float xi[256], q[256], lg[128], sred[2];
    xi[tid] = text[(size_t)bid * 256 + tid];
    __syncthreads();
    float acc = 0.f;
    #pragma unroll 4
    for (int k = 0; k < 256; k++) acc = fmaf(xi[k], AL[k * 256 + tid], acc);
    q[tid] = acc;
    __syncthreads();

    int w = tid >> 5, lane = tid & 31;
    for (int j = w * 16; j < w * 16 + 16; j++) {
        const float* tj = text + (size_t)(b * 128 + j) * 256;
        float a = 0.f;
        #pragma unroll
        for (int t = 0; t < 8; t++) {
            int d = lane + 32 * t;
            a = fmaf(q[d], tj[d], a);
        }
        #pragma unroll
        for (int o = 16; o; o >>= 1) a += __shfl_xor_sync(0xffffffffu, a, o);
        if (lane == 0)
            lg[j] = a + (1.0f - textmask[b * 128 + j]) * -1e20f;
    }
    __syncthreads();
    if (tid < 32) {
        float m = -3.4e38f;
        for (int k = tid; k < 128; k += 32) m = fmaxf(m, lg[k]);
        #pragma unroll
        for (int o = 16; o; o >>= 1) m = fmaxf(m, __shfl_xor_sync(0xffffffffu, m, o));
        if (tid == 0) sred[0] = m;
    }
    __syncthreads();
    float mx = sred[0];
    if (tid < 128) lg[tid] = __expf(lg[tid] - mx);
    __syncthreads();
    if (tid < 32) {
        float s = 0.f;
        for (int k = tid; k < 128; k += 32) s += lg[k];
        #pragma unroll
        for (int o = 16; o; o >>= 1) s += __shfl_xor_sync(0xffffffffu, s, o);
        if (tid == 0) sred[1] = s;
    }
    __syncthreads();
    float inv = 1.0f / sred[1];
    float a2 = 0.f;
    for (int j = 0; j < 128; j++)
        a2 = fmaf(lg[j], text[(size_t)(b * 128 + j) * 256 + tid], a2);
    outss[(size_t)bid * 256 + tid] = a2 * inv * textmask[bid] + abias[tid];
}

// ---------------- launch ------------------------------------------------------
#define F32A_SMEM 92160   // 3*(128*40*4) + 3*(128*40*2)

extern "C" void kernel_launch(void* const* d_in, const int* in_sizes, int n_in,
                              void* d_out, int out_size) {
    const float* text      = (const float*)d_in[0];
    const float* adj1      = (const float*)d_in[1];
    const float* adj2      = (const float*)d_in[2];
    const float* edge1     = (const float*)d_in[3];
    const float* edge2     = (const float*)d_in[4];
    const float* textmask  = (const float*)d_in[5];
    const float* weight    = (const float*)d_in[6];
    const float* bias      = (const float*)d_in[7];
    const float* gamma     = (const float*)d_in[8];
    const float* beta      = (const float*)d_in[9];
    const float* fuse1_w   = (const float*)d_in[10];
    const float* fuse2_w   = (const float*)d_in[11];
    const float* fc3_w     = (const float*)d_in[12];
    const float* fc1_w0    = (const float*)d_in[13];
    const float* fc1_w1    = (const float*)d_in[14];
    const float* fc1_b1    = (const float*)d_in[15];
    const float* fc2_w0    = (const float*)d_in[16];
    const float* fc2_w1    = (const float*)d_in[17];
    const float* fc2_b1    = (const float*)d_in[18];
    const float* align_lin = (const float*)d_in[19];
    const float* align_bias= (const float*)d_in[20];
    float* out = (float*)d_out;

    static int attr_done = 0;
    if (!attr_done) {
        cudaFuncSetAttribute(hgemm_f32a,
                             cudaFuncAttributeMaxDynamicSharedMemorySize,
                             F32A_SMEM);
        attr_done = 1;
    }

    __half *p_pre1, *p_pre2, *p_Wh1, *p_Wh2, *p_WhP, *p_Wh3,
           *p_Whw, *p_t16, *p_P16, *p_out16, *p_OC16;
    float *p_out, *p_H;
    cudaGetSymbolAddress((void**)&p_pre1,  g_pre1h);
    cudaGetSymbolAddress((void**)&p_pre2,  g_pre2h);
    cudaGetSymbolAddress((void**)&p_Wh1,   g_Wh1);
    cudaGetSymbolAddress((void**)&p_Wh2,   g_Wh2);
    cudaGetSymbolAddress((void**)&p_WhP,   g_WhP);
    cudaGetSymbolAddress((void**)&p_Wh3,   g_Wh3);
    cudaGetSymbolAddress((void**)&p_Whw,   g_Whw);
    cudaGetSymbolAddress((void**)&p_t16,   g_text16);
    cudaGetSymbolAddress((void**)&p_P16,   g_P16);
    cudaGetSymbolAddress((void**)&p_out16, g_out16);
    cudaGetSymbolAddress((void**)&p_OC16,  g_OC16);
    cudaGetSymbolAddress((void**)&p_out,   g_out);
    cudaGetSymbolAddress((void**)&p_H,     g_H);

    // (1) weight repacks + text16 in one launch
    repack_all_h<<<dim3(256, 13), 256>>>(weight, fuse1_w, fuse2_w, fc3_w,
                                         fc1_w0, fc2_w0, text);

    // (2) out = relu(text @ weight), fp32 + fp16
    hgemm<<<dim3(2, 8), 256>>>(p_t16, p_Whw, p_out, p_out16, BN2, 256, 256, 1);

    // (3) independent self-alignment output
    align_kernel<<<BN2, 256>>>(text, textmask, align_lin, align_bias,
                               out + BN2 * 256);

    // (4,5) loop-invariant edge projections, 3-stage pipeline
    hgemm_f32a<<<dim3(4, 1024), 256, F32A_SMEM>>>(edge1, p_Wh1, p_pre1,
                                                  ROWS_E, 512, 256);
    hgemm_f32a<<<dim3(4, 1024), 256, F32A_SMEM>>>(edge2, p_Wh2, p_pre2,
                                                  ROWS_E, 512, 256);

    for (int it = 0; it < 3; it++) {
        // P16 = out @ Wproj
        hgemm<<<dim3(12, 8), 256>>>(p_out16, p_WhP, (float*)0, p_P16,
                                    BN2, 1536, 256, 0);
        scoreagg_kernel<<<BN2, 256>>>(p_P16, adj1, adj2, fc1_w1, fc2_w1,
                                      fc1_b1, fc2_b1, p_OC16);
        // H = [out1|out2] @ fc3_w
        hgemm<<<dim3(2, 8), 256>>>(p_OC16, p_Wh3, p_H, (__half*)0,
                                   BN2, 256, 512, 0);
        float* dst = (it == 2) ? out : p_out;
        ln_kernel<<<BN2, 256>>>(p_H, p_out, bias, gamma, beta, dst, p_out16);
    }
}

// round 16
// speedup vs baseline: 1.4842x; 1.0199x over previous
#include <cuda_runtime.h>
#include <cuda_fp16.h>
#include <math.h>
#include <stdint.h>

// B=8, N=128, D=256
#define BN2 1024           // B*N
#define ROWS_E 131072      // B*N*N

// ---------------- scratch (device globals; no allocation allowed) -------------
__device__ __align__(16) __half g_pre1h[67108864]; // [B*N*N,512]: 0..255 fuse, 256..511 fc
__device__ __align__(16) __half g_pre2h[67108864];
__device__ __align__(16) __half g_Wh1[512 * 256];  // fp16 [N][K]
__device__ __align__(16) __half g_Wh2[512 * 256];
__device__ __align__(16) __half g_WhP[1536 * 256];
__device__ __align__(16) __half g_Wh3[256 * 512];
__device__ __align__(16) __half g_Whw[256 * 256];
__device__ __align__(16) __half g_text16[1024 * 256];
__device__ __align__(16) __half g_P16[1024 * 1536]; // [A1|B1|A2|B2|U1|U2]
__device__ __align__(16) __half g_out16[1024 * 256];
__device__ __align__(16) __half g_OC16[1024 * 512]; // [out1|out2]
__device__ float g_out[1024 * 256];
__device__ float g_H[1024 * 256];

// ---------------- helpers ----------------------------------------------------
__device__ __forceinline__ float blockSum256(float v) {
    __shared__ float red[8];
    #pragma unroll
    for (int o = 16; o; o >>= 1) v += __shfl_xor_sync(0xffffffffu, v, o);
    if ((threadIdx.x & 31) == 0) red[threadIdx.x >> 5] = v;
    __syncthreads();
    float s = red[0];
    #pragma unroll
    for (int k = 1; k < 8; k++) s += red[k];
    __syncthreads();
    return s;
}

__device__ __forceinline__ void mma_f16(float* d, const uint32_t* a, const uint32_t* b) {
    asm volatile(
        "mma.sync.aligned.m16n8k16.row.col.f32.f16.f16.f32 "
        "{%0,%1,%2,%3}, {%4,%5,%6,%7}, {%8,%9}, {%0,%1,%2,%3};\n"
        : "+f"(d[0]), "+f"(d[1]), "+f"(d[2]), "+f"(d[3])
        : "r"(a[0]), "r"(a[1]), "r"(a[2]), "r"(a[3]), "r"(b[0]), "r"(b[1]));
}

__device__ __forceinline__ void cp16(uint32_t dst, const void* src) {
    asm volatile("cp.async.cg.shared.global [%0], [%1], 16;\n" :: "r"(dst), "l"(src));
}

__device__ __forceinline__ uint32_t pack_h2(float a, float b) {
    __half2 h = __floats2half2_rn(a, b);
    return *(uint32_t*)&h;
}

// ---------------- weight repack (fp16, [N][K]) + text conversion --------------
__global__ void repack_all_h(const float* __restrict__ weight,
                             const float* __restrict__ fuse1_w,
                             const float* __restrict__ fuse2_w,
                             const float* __restrict__ fc3_w,
                             const float* __restrict__ fc1_w0,
                             const float* __restrict__ fc2_w0,
                             const float* __restrict__ text) {
    int n = blockIdx.x;     // 0..255
    int k = threadIdx.x;    // 0..255
    int seg = blockIdx.y;   // 0..12
    const float* src;
    __half* dst;
    switch (seg) {
        case 0:  src = fuse1_w + 256 * 256; dst = g_Wh1;              break;
        case 1:  src = fc1_w0 + 512 * 256;  dst = g_Wh1 + 256 * 256;  break;
        case 2:  src = fuse2_w + 256 * 256; dst = g_Wh2;              break;
        case 3:  src = fc2_w0 + 512 * 256;  dst = g_Wh2 + 256 * 256;  break;
        case 4:  src = fc1_w0;              dst = g_WhP;              break;
        case 5:  src = fc1_w0 + 256 * 256;  dst = g_WhP + 256 * 256;  break;
        case 6:  src = fc2_w0;              dst = g_WhP + 512 * 256;  break;
        case 7:  src = fc2_w0 + 256 * 256;  dst = g_WhP + 768 * 256;  break;
        case 8:  src = fuse1_w;             dst = g_WhP + 1024 * 256; break;
        case 9:  src = fuse2_w;             dst = g_WhP + 1280 * 256; break;
        case 10: src = weight;              dst = g_Whw;              break;
        case 11: // fc3: K = 512
            g_Wh3[n * 512 + k]       = __float2half(fc3_w[k * 256 + n]);
            g_Wh3[n * 512 + k + 256] = __float2half(fc3_w[(k + 256) * 256 + n]);
            return;
        default: // text conversion
            g_text16[n * 1024 + k]       = __float2half(text[n * 1024 + k]);
            g_text16[n * 1024 + 256 + k] = __float2half(text[n * 1024 + 256 + k]);
            g_text16[n * 1024 + 512 + k] = __float2half(text[n * 1024 + 512 + k]);
            g_text16[n * 1024 + 768 + k] = __float2half(text[n * 1024 + 768 + k]);
            return;
    }
    dst[n * 256 + k] = __float2half(src[k * 256 + n]);
}

// ---------------- fp16 tensor GEMM (small shapes): C = A_h @ Wt^T -------------
#define HSTAGE 5120             // halfs per stage per matrix (128*40)
__global__ __launch_bounds__(256, 2) void hgemm(
    const __half* __restrict__ A, const __half* __restrict__ Wt,
    float* __restrict__ C, __half* __restrict__ Ch,
    int M, int N, int K, int doRelu) {
    __shared__ __half As[2][128][40];
    __shared__ __half Bs[2][128][40];
    const int tid = threadIdx.x;
    const int wid = tid >> 5, lane = tid & 31;
    const int g = lane >> 2, qt = lane & 3;
    const int warp_m = wid & 1, warp_n = wid >> 1;
    const int row0 = blockIdx.y * 128;
    const int col0 = blockIdx.x * 128;

    const uint32_t aAddr = (uint32_t)__cvta_generic_to_shared(&As[0][0][0]);
    const uint32_t bAddr = (uint32_t)__cvta_generic_to_shared(&Bs[0][0][0]);
    const int ldr = tid >> 2;          // 0..63
    const int ldc = (tid & 3) * 8;     // 0,8,16,24

    float acc[4][4][4];
    #pragma unroll
    for (int i = 0; i < 4; i++)
        #pragma unroll
        for (int j = 0; j < 4; j++)
            #pragma unroll
            for (int r = 0; r < 4; r++) acc[i][j][r] = 0.f;

    const int KT = K >> 5;

    #pragma unroll
    for (int i = 0; i < 2; i++) {
        int r = ldr + 64 * i;
        cp16(aAddr + (uint32_t)(r * 40 + ldc) * 2, A + (size_t)(row0 + r) * K + ldc);
        cp16(bAddr + (uint32_t)(r * 40 + ldc) * 2, Wt + (size_t)(col0 + r) * K + ldc);
    }
    asm volatile("cp.async.commit_group;\n");

    for (int kt = 0; kt < KT; kt++) {
        if (kt + 1 < KT) {
            int kk = (kt + 1) << 5;
            uint32_t so = (uint32_t)(((kt + 1) & 1) * HSTAGE * 2);
            #pragma unroll
            for (int i = 0; i < 2; i++) {
                int r = ldr + 64 * i;
                cp16(aAddr + so + (uint32_t)(r * 40 + ldc) * 2,
                     A + (size_t)(row0 + r) * K + kk + ldc);
                cp16(bAddr + so + (uint32_t)(r * 40 + ldc) * 2,
                     Wt + (size_t)(col0 + r) * K + kk + ldc);
            }
            asm volatile("cp.async.commit_group;\n");
            asm volatile("cp.async.wait_group 1;\n");
        } else {
            asm volatile("cp.async.wait_group 0;\n");
        }
        __syncthreads();

        const __half* Ac = &As[kt & 1][0][0];
        const __half* Bc = &Bs[kt & 1][0][0];
        #pragma unroll
        for (int ks = 0; ks < 2; ks++) {
            int ko = ks * 16;
            uint32_t af[4][4], bfr[4][2];
            #pragma unroll
            for (int mt = 0; mt < 4; mt++) {
                int R = warp_m * 64 + mt * 16 + g;
                af[mt][0] = *(const uint32_t*)&Ac[R * 40 + ko + 2 * qt];
                af[mt][1] = *(const uint32_t*)&Ac[(R + 8) * 40 + ko + 2 * qt];
                af[mt][2] = *(const uint32_t*)&Ac[R * 40 + ko + 2 * qt + 8];
                af[mt][3] = *(const uint32_t*)&Ac[(R + 8) * 40 + ko + 2 * qt + 8];
            }
            #pragma unroll
            for (int nt = 0; nt < 4; nt++) {
                int Cc = warp_n * 32 + nt * 8 + g;
                bfr[nt][0] = *(const uint32_t*)&Bc[Cc * 40 + ko + 2 * qt];
                bfr[nt][1] = *(const uint32_t*)&Bc[Cc * 40 + ko + 2 * qt + 8];
            }
            #pragma unroll
            for (int mt = 0; mt < 4; mt++)
                #pragma unroll
                for (int nt = 0; nt < 4; nt++)
                    mma_f16(acc[mt][nt], af[mt], bfr[nt]);
        }
        __syncthreads();
    }

    #pragma unroll
    for (int mt = 0; mt < 4; mt++) {
        int R = row0 + warp_m * 64 + mt * 16 + g;
        #pragma unroll
        for (int nt = 0; nt < 4; nt++) {
            int Cc = col0 + warp_n * 32 + nt * 8 + 2 * qt;
            float c0 = acc[mt][nt][0], c1 = acc[mt][nt][1];
            float c2 = acc[mt][nt][2], c3 = acc[mt][nt][3];
            if (doRelu) {
                c0 = fmaxf(c0, 0.f); c1 = fmaxf(c1, 0.f);
                c2 = fmaxf(c2, 0.f); c3 = fmaxf(c3, 0.f);
            }
            if (C) {
                float2 v0 = {c0, c1}, v1 = {c2, c3};
                *(float2*)(C + (size_t)R * N + Cc) = v0;
                *(float2*)(C + (size_t)(R + 8) * N + Cc) = v1;
            }
            if (Ch) {
                *(__half2*)(Ch + (size_t)R * N + Cc) = __floats2half2_rn(c0, c1);
                *(__half2*)(Ch + (size_t)(R + 8) * N + Cc) = __floats2half2_rn(c2, c3);
            }
        }
    }
}

// ---------------- fp32-A fp16 GEMM (edge projections), 3-stage pipeline -------
// 128x128 tile, BK=32, warp grid 4x2 (warp tile 32x64). A fp32 via cp.async
// (rounded at fragment load), B fp16 via cp.async. Prefetch distance 2.
#define ASTG 5120               // floats per A stage (128*40)
#define BSTG 5120               // halfs per B stage (128*40)
__global__ __launch_bounds__(256, 2) void hgemm_f32a(
    const float* __restrict__ A, const __half* __restrict__ Wt,
    __half* __restrict__ Ch, int M, int N, int K) {
    extern __shared__ uint32_t sh[];
    float* As = (float*)sh;                    // [3][128][40] fp32
    __half* Bs = (__half*)(sh + 3 * ASTG);     // [3][128][40] fp16
    const int tid = threadIdx.x;
    const int wid = tid >> 5, lane = tid & 31;
    const int g = lane >> 2, qt = lane & 3;
    const int warp_m = wid >> 1;       // 0..3  (32-row slab)
    const int warp_n = wid & 1;        // 0..1  (64-col slab)
    const int row0 = blockIdx.y * 128;
    const int col0 = blockIdx.x * 128;

    const uint32_t aAddr = (uint32_t)__cvta_generic_to_shared(As);
    const uint32_t bAddr = (uint32_t)__cvta_generic_to_shared(Bs);
    const int ldrA = tid >> 3;         // 0..31
    const int ldcA = (tid & 7) * 4;    // floats
    const int ldrB = tid >> 2;         // 0..63
    const int ldcB = (tid & 3) * 8;    // halfs

    float acc[2][8][4];
    #pragma unroll
    for (int i = 0; i < 2; i++)
        #pragma unroll
        for (int j = 0; j < 8; j++)
            #pragma unroll
            for (int r = 0; r < 4; r++) acc[i][j][r] = 0.f;

    const int KT = K >> 5;   // 8

    // prologue: fill stages 0 and 1
    #pragma unroll
    for (int s = 0; s < 2; s++) {
        int kk = s << 5;
        uint32_t soA = (uint32_t)(s * ASTG * 4);
        uint32_t soB = (uint32_t)(s * BSTG * 2);
        #pragma unroll
        for (int i = 0; i < 4; i++) {
            int r = ldrA + 32 * i;
            cp16(aAddr + soA + (uint32_t)(r * 40 + ldcA) * 4,
                 A + (size_t)(row0 + r) * K + kk + ldcA);
        }
        #pragma unroll
        for (int i = 0; i < 2; i++) {
            int r = ldrB + 64 * i;
            cp16(bAddr + soB + (uint32_t)(r * 40 + ldcB) * 2,
                 Wt + (size_t)(col0 + r) * K + kk + ldcB);
        }
        asm volatile("cp.async.commit_group;\n");
    }

    for (int kt = 0; kt < KT; kt++) {
        if (kt + 2 < KT) {
            int kk = (kt + 2) << 5;
            int st = (kt + 2) % 3;
            uint32_t soA = (uint32_t)(st * ASTG * 4);
            uint32_t soB = (uint32_t)(st * BSTG * 2);
            #pragma unroll
            for (int i = 0; i < 4; i++) {
                int r = ldrA + 32 * i;
                cp16(aAddr + soA + (uint32_t)(r * 40 + ldcA) * 4,
                     A + (size_t)(row0 + r) * K + kk + ldcA);
            }
            #pragma unroll
            for (int i = 0; i < 2; i++) {
                int r = ldrB + 64 * i;
                cp16(bAddr + soB + (uint32_t)(r * 40 + ldcB) * 2,
                     Wt + (size_t)(col0 + r) * K + kk + ldcB);
            }
            asm volatile("cp.async.commit_group;\n");
            asm volatile("cp.async.wait_group 2;\n");
        } else if (kt + 1 < KT) {
            asm volatile("cp.async.wait_group 1;\n");
        } else {
            asm volatile("cp.async.wait_group 0;\n");
        }
        __syncthreads();

        const int st = kt % 3;
        const float* Ac = As + st * ASTG;
        const __half* Bc = Bs + st * BSTG;
        #pragma unroll
        for (int ks = 0; ks < 2; ks++) {
            int ko = ks * 16;
            uint32_t af[2][4], bfr[8][2];
            #pragma unroll
            for (int mt = 0; mt < 2; mt++) {
                int R = warp_m * 32 + mt * 16 + g;
                float2 v0 = *(const float2*)&Ac[R * 40 + ko + 2 * qt];
                float2 v1 = *(const float2*)&Ac[(R + 8) * 40 + ko + 2 * qt];
                float2 v2 = *(const float2*)&Ac[R * 40 + ko + 2 * qt + 8];
                float2 v3 = *(const float2*)&Ac[(R + 8) * 40 + ko + 2 * qt + 8];
                af[mt][0] = pack_h2(v0.x, v0.y);
                af[mt][1] = pack_h2(v1.x, v1.y);
                af[mt][2] = pack_h2(v2.x, v2.y);
                af[mt][3] = pack_h2(v3.x, v3.y);
            }
            #pragma unroll
            for (int nt = 0; nt < 8; nt++) {
                int Cc = warp_n * 64 + nt * 8 + g;
                bfr[nt][0] = *(const uint32_t*)&Bc[Cc * 40 + ko + 2 * qt];
                bfr[nt][1] = *(const uint32_t*)&Bc[Cc * 40 + ko + 2 * qt + 8];
            }
            #pragma unroll
            for (int mt = 0; mt < 2; mt++)
                #pragma unroll
                for (int nt = 0; nt < 8; nt++)
                    mma_f16(acc[mt][nt], af[mt], bfr[nt]);
        }
        __syncthreads();
    }

    #pragma unroll
    for (int mt = 0; mt < 2; mt++) {
        int R = row0 + warp_m * 32 + mt * 16 + g;
        #pragma unroll
        for (int nt = 0; nt < 8; nt++) {
            int Cc = col0 + warp_n * 64 + nt * 8 + 2 * qt;
            *(__half2*)(Ch + (size_t)R * N + Cc) =
                __floats2half2_rn(acc[mt][nt][0], acc[mt][nt][1]);
            *(__half2*)(Ch + (size_t)(R + 8) * N + Cc) =
                __floats2half2_rn(acc[mt][nt][2], acc[mt][nt][3]);
        }
    }
}

// ---------------- fused score + aggregate: one block per (b,i) ----------------
__global__ __launch_bounds__(256) void scoreagg_kernel(
    const __half* __restrict__ P,
    const float* __restrict__ adj1, const float* __restrict__ adj2,
    const float* __restrict__ fc1_w1, const float* __restrict__ fc2_w1,
    const float* __restrict__ fc1_b1, const float* __restrict__ fc2_b1,
    __half* __restrict__ OC) {
    int bid = blockIdx.x;            // b*N + i
    int b = bid >> 7;
    int tid = threadIdx.x, wid = tid >> 5, lane = tid & 31;
    __shared__ __half2 PiA[256];
    __shared__ float w1s[128], w2s[128], sred[8];

    const __half* Pi = P + (size_t)bid * 1536;
    float d1 = 0.f, d2 = 0.f;
    if (tid < 128) {
        PiA[tid]       = *(const __half2*)&Pi[2 * tid];          // A1
        PiA[128 + tid] = *(const __half2*)&Pi[512 + 2 * tid];    // A2
        d1 = adj1[bid * 128 + tid];
        d2 = adj2[bid * 128 + tid];
    }
    #pragma unroll
    for (int o = 16; o; o >>= 1) {
        d1 += __shfl_xor_sync(0xffffffffu, d1, o);
        d2 += __shfl_xor_sync(0xffffffffu, d2, o);
    }
    if (tid < 128 && lane == 0) { sred[wid] = d1; sred[4 + wid] = d2; }
    __syncthreads();
    float denom1 = sred[0] + sred[1] + sred[2] + sred[3] + 1.0f;
    float denom2 = sred[4] + sred[5] + sred[6] + sred[7] + 1.0f;
    float bb1 = fc1_b1[0], bb2 = fc2_b1[0];

    // phase 1: scores (8 warps x 16 j)
    for (int jj = 0; jj < 16; jj++) {
        int j = wid * 16 + jj;
        const __half2* Pj = (const __half2*)(P + (size_t)(b * 128 + j) * 1536);
        const __half2* e1 = (const __half2*)(g_pre1h + ((size_t)bid * 128 + j) * 512 + 256);
        const __half2* e2 = (const __half2*)(g_pre2h + ((size_t)bid * 128 + j) * 512 + 256);
        float s1 = 0.f, s2 = 0.f;
        #pragma unroll
        for (int t = 0; t < 4; t++) {
            int p = lane + 32 * t;
            float2 a1 = __half22float2(PiA[p]);
            float2 a2 = __half22float2(PiA[128 + p]);
            float2 b1v = __half22float2(Pj[128 + p]);  // B1
            float2 b2v = __half22float2(Pj[384 + p]);  // B2
            float2 f1 = __half22float2(e1[p]);
            float2 f2 = __half22float2(e2[p]);
            float2 w1 = *(const float2*)&fc1_w1[2 * p];
            float2 w2 = *(const float2*)&fc2_w1[2 * p];
            s1 = fmaf(fmaxf(a1.x + b1v.x + f1.x, 0.f), w1.x, s1);
            s1 = fmaf(fmaxf(a1.y + b1v.y + f1.y, 0.f), w1.y, s1);
            s2 = fmaf(fmaxf(a2.x + b2v.x + f2.x, 0.f), w2.x, s2);
            s2 = fmaf(fmaxf(a2.y + b2v.y + f2.y, 0.f), w2.y, s2);
        }
        #pragma unroll
        for (int o = 16; o; o >>= 1) {
            s1 += __shfl_xor_sync(0xffffffffu, s1, o);
            s2 += __shfl_xor_sync(0xffffffffu, s2, o);
        }
        if (lane == 0) {
            w1s[j] = adj1[bid * 128 + j] / (1.f + __expf(-(s1 + bb1)));
            w2s[j] = adj2[bid * 128 + j] / (1.f + __expf(-(s2 + bb2)));
        }
    }
    __syncthreads();

    // phase 2: half the threads per matrix, half2-vectorized over d.
    // Per-d accumulation order identical to the scalar version (bitwise same).
    int half_id = tid >> 7;          // 0 -> out1, 1 -> out2
    int dt = tid & 127;              // d-pair index
    const __half2* U = (const __half2*)(P + (size_t)(b * 128) * 1536
                                        + (half_id ? 1280 : 1024));
    const __half2* E = (const __half2*)((half_id ? g_pre2h : g_pre1h)
                                        + (size_t)bid * 128 * 512);
    const float* ws = half_id ? w2s : w1s;
    float inv = 1.0f / (half_id ? denom2 : denom1);
    float2 acc = {0.f, 0.f};
    #pragma unroll 4
    for (int j = 0; j < 128; j++) {
        float2 u = __half22float2(U[j * 768 + dt]);
        float2 f = __half22float2(E[j * 256 + dt]);
        float w = ws[j];
        acc.x = fmaf(w, fmaxf(u.x + f.x, 0.f), acc.x);
        acc.y = fmaf(w, fmaxf(u.y + f.y, 0.f), acc.y);
    }
    *(__half2*)&OC[(size_t)bid * 512 + half_id * 256 + 2 * dt] =
        __floats2half2_rn(acc.x * inv, acc.y * inv);
}

// ---------------- relu + residual + bias + layernorm --------------------------
__global__ __launch_bounds__(256) void ln_kernel(
    const float* __restrict__ H, const float* __restrict__ prev,
    const float* __restrict__ bias, const float* __restrict__ gamma,
    const float* __restrict__ beta, float* __restrict__ dst,
    __half* __restrict__ dst16) {
    int row = blockIdx.x, tid = threadIdx.x;
    float v = fmaxf(H[(size_t)row * 256 + tid], 0.f)
              + prev[(size_t)row * 256 + tid] + bias[tid];
    float mean = blockSum256(v) * (1.0f / 256.0f);
    float c = v - mean;
    float var = blockSum256(c * c) * (1.0f / 256.0f);
    float r = c * rsqrtf(var + 1e-5f) * gamma[tid] + beta[tid];
    dst[(size_t)row * 256 + tid] = r;
    dst16[(size_t)row * 256 + tid] = __float2half(r);
}

// ---------------- self-alignment: outss --------------------------------------
__global__ __launch_bounds__(256) void align_kernel(
    const float* __restrict__ text, const float* __restrict__ textmask,
    const float* __restrict__ AL, const float* __restrict__ abias,
    float* __restrict__ outss) {
    int bid = blockIdx.x;    // b*N + i
    int b = bid >> 7;
    int tid = threadIdx.x;
    __shared__ float xi[256], q[256], lg[128], sred[2];
    xi[tid] = text[(size_t)bid * 256 + tid];
    __syncthreads();
    float acc = 0.f;
    #pragma unroll 4
    for (int k = 0; k < 256; k++) acc = fmaf(xi[k], AL[k * 256 + tid], acc);
    q[tid] = acc;
    __syncthreads();

    int w = tid >> 5, lane = tid & 31;
    for (int j = w * 16; j < w * 16 + 16; j++) {
        const float* tj = text + (size_t)(b * 128 + j) * 256;
        float a = 0.f;
        #pragma unroll
        for (int t = 0; t < 8; t++) {
            int d = lane + 32 * t;
            a = fmaf(q[d], tj[d], a);
        }
        #pragma unroll
        for (int o = 16; o; o >>= 1) a += __shfl_xor_sync(0xffffffffu, a, o);
        if (lane == 0)
            lg[j] = a + (1.0f - textmask[b * 128 + j]) * -1e20f;
    }
    __syncthreads();
    if (tid < 32) {
        float m = -3.4e38f;
        for (int k = tid; k < 128; k += 32) m = fmaxf(m, lg[k]);
        #pragma unroll
        for (int o = 16; o; o >>= 1) m = fmaxf(m, __shfl_xor_sync(0xffffffffu, m, o));
        if (tid == 0) sred[0] = m;
    }
    __syncthreads();
    float mx = sred[0];
    if (tid < 128) lg[tid] = __expf(lg[tid] - mx);
    __syncthreads();
    if (tid < 32) {
        float s = 0.f;
        for (int k = tid; k < 128; k += 32) s += lg[k];
        #pragma unroll
        for (int o = 16; o; o >>= 1) s += __shfl_xor_sync(0xffffffffu, s, o);
        if (tid == 0) sred[1] = s;
    }
    __syncthreads();
    float inv = 1.0f / sred[1];
    float a2 = 0.f;
    for (int j = 0; j < 128; j++)
        a2 = fmaf(lg[j], text[(size_t)(b * 128 + j) * 256 + tid], a2);
    outss[(size_t)bid * 256 + tid] = a2 * inv * textmask[bid] + abias[tid];
}

// ---------------- launch ------------------------------------------------------
#define F32A_SMEM 92160   // 3*(128*40*4) + 3*(128*40*2)

extern "C" void kernel_launch(void* const* d_in, const int* in_sizes, int n_in,
                              void* d_out, int out_size) {
    const float* text      = (const float*)d_in[0];
    const float* adj1      = (const float*)d_in[1];
    const float* adj2      = (const float*)d_in[2];
    const float* edge1     = (const float*)d_in[3];
    const float* edge2     = (const float*)d_in[4];
    const float* textmask  = (const float*)d_in[5];
    const float* weight    = (const float*)d_in[6];
    const float* bias      = (const float*)d_in[7];
    const float* gamma     = (const float*)d_in[8];
    const float* beta      = (const float*)d_in[9];
    const float* fuse1_w   = (const float*)d_in[10];
    const float* fuse2_w   = (const float*)d_in[11];
    const float* fc3_w     = (const float*)d_in[12];
    const float* fc1_w0    = (const float*)d_in[13];
    const float* fc1_w1    = (const float*)d_in[14];
    const float* fc1_b1    = (const float*)d_in[15];
    const float* fc2_w0    = (const float*)d_in[16];
    const float* fc2_w1    = (const float*)d_in[17];
    const float* fc2_b1    = (const float*)d_in[18];
    const float* align_lin = (const float*)d_in[19];
    const float* align_bias= (const float*)d_in[20];
    float* out = (float*)d_out;

    static int attr_done = 0;
    if (!attr_done) {
        cudaFuncSetAttribute(hgemm_f32a,
                             cudaFuncAttributeMaxDynamicSharedMemorySize,
                             F32A_SMEM);
        attr_done = 1;
    }

    __half *p_pre1, *p_pre2, *p_Wh1, *p_Wh2, *p_WhP, *p_Wh3,
           *p_Whw, *p_t16, *p_P16, *p_out16, *p_OC16;
    float *p_out, *p_H;
    cudaGetSymbolAddress((void**)&p_pre1,  g_pre1h);
    cudaGetSymbolAddress((void**)&p_pre2,  g_pre2h);
    cudaGetSymbolAddress((void**)&p_Wh1,   g_Wh1);
    cudaGetSymbolAddress((void**)&p_Wh2,   g_Wh2);
    cudaGetSymbolAddress((void**)&p_WhP,   g_WhP);
    cudaGetSymbolAddress((void**)&p_Wh3,   g_Wh3);
    cudaGetSymbolAddress((void**)&p_Whw,   g_Whw);
    cudaGetSymbolAddress((void**)&p_t16,   g_text16);
    cudaGetSymbolAddress((void**)&p_P16,   g_P16);
    cudaGetSymbolAddress((void**)&p_out16, g_out16);
    cudaGetSymbolAddress((void**)&p_OC16,  g_OC16);
    cudaGetSymbolAddress((void**)&p_out,   g_out);
    cudaGetSymbolAddress((void**)&p_H,     g_H);

    // (1) weight repacks + text16 in one launch
    repack_all_h<<<dim3(256, 13), 256>>>(weight, fuse1_w, fuse2_w, fc3_w,
                                         fc1_w0, fc2_w0, text);

    // (2) out = relu(text @ weight), fp32 + fp16
    hgemm<<<dim3(2, 8), 256>>>(p_t16, p_Whw, p_out, p_out16, BN2, 256, 256, 1);

    // (3,4) loop-invariant edge projections, 3-stage pipeline
    hgemm_f32a<<<dim3(4, 1024), 256, F32A_SMEM>>>(edge1, p_Wh1, p_pre1,
                                                  ROWS_E, 512, 256);
    hgemm_f32a<<<dim3(4, 1024), 256, F32A_SMEM>>>(edge2, p_Wh2, p_pre2,
                                                  ROWS_E, 512, 256);

    for (int it = 0; it < 3; it++) {
        // (5) P16 = out @ Wproj
        hgemm<<<dim3(12, 8), 256>>>(p_out16, p_WhP, (float*)0, p_P16,
                                    BN2, 1536, 256, 0);
        // (6) fused score + aggregate  <- ncu -s 5 -c 1 lands here (iter 0)
        scoreagg_kernel<<<BN2, 256>>>(p_P16, adj1, adj2, fc1_w1, fc2_w1,
                                      fc1_b1, fc2_b1, p_OC16);
        // (7) H = [out1|out2] @ fc3_w
        hgemm<<<dim3(2, 8), 256>>>(p_OC16, p_Wh3, p_H, (__half*)0,
                                   BN2, 256, 512, 0);
        float* dst = (it == 2) ? out : p_out;
        ln_kernel<<<BN2, 256>>>(p_H, p_out, bias, gamma, beta, dst, p_out16);
    }

    // independent self-alignment output (moved after loop; no deps)
    align_kernel<<<BN2, 256>>>(text, textmask, align_lin, align_bias,
                               out + BN2 * 256);
}

// round 17
// speedup vs baseline: 1.6675x; 1.1235x over previous
#include <cuda_runtime.h>
#include <cuda_fp16.h>
#include <math.h>
#include <stdint.h>

// B=8, N=128, D=256
#define BN2 1024           // B*N
#define ROWS_E 131072      // B*N*N

// ---------------- scratch (device globals; no allocation allowed) -------------
__device__ __align__(16) __half g_pre1h[67108864]; // [B*N*N,512]: 0..255 fuse, 256..511 fc
__device__ __align__(16) __half g_pre2h[67108864];
__device__ __align__(16) __half g_Wh1[512 * 256];  // fp16 [N][K]
__device__ __align__(16) __half g_Wh2[512 * 256];
__device__ __align__(16) __half g_WhP[1536 * 256];
__device__ __align__(16) __half g_Wh3[256 * 512];
__device__ __align__(16) __half g_Whw[256 * 256];
__device__ __align__(16) __half g_text16[1024 * 256];
__device__ __align__(16) __half g_P16[1024 * 1536]; // [A1|B1|A2|B2|U1|U2]
__device__ __align__(16) __half g_out16[1024 * 256];
__device__ __align__(16) __half g_OC16[1024 * 512]; // [out1|out2]
__device__ float g_out[1024 * 256];
__device__ float g_H[1024 * 256];

// ---------------- helpers ----------------------------------------------------
__device__ __forceinline__ float blockSum256(float v) {
    __shared__ float red[8];
    #pragma unroll
    for (int o = 16; o; o >>= 1) v += __shfl_xor_sync(0xffffffffu, v, o);
    if ((threadIdx.x & 31) == 0) red[threadIdx.x >> 5] = v;
    __syncthreads();
    float s = red[0];
    #pragma unroll
    for (int k = 1; k < 8; k++) s += red[k];
    __syncthreads();
    return s;
}

__device__ __forceinline__ void mma_f16(float* d, const uint32_t* a, const uint32_t* b) {
    asm volatile(
        "mma.sync.aligned.m16n8k16.row.col.f32.f16.f16.f32 "
        "{%0,%1,%2,%3}, {%4,%5,%6,%7}, {%8,%9}, {%0,%1,%2,%3};\n"
        : "+f"(d[0]), "+f"(d[1]), "+f"(d[2]), "+f"(d[3])
        : "r"(a[0]), "r"(a[1]), "r"(a[2]), "r"(a[3]), "r"(b[0]), "r"(b[1]));
}

__device__ __forceinline__ void cp16(uint32_t dst, const void* src) {
    asm volatile("cp.async.cg.shared.global [%0], [%1], 16;\n" :: "r"(dst), "l"(src));
}

__device__ __forceinline__ uint32_t pack_h2(float a, float b) {
    __half2 h = __floats2half2_rn(a, b);
    return *(uint32_t*)&h;
}

// ---------------- weight repack (fp16, [N][K]) + text conversion --------------
__global__ void repack_all_h(const float* __restrict__ weight,
                             const float* __restrict__ fuse1_w,
                             const float* __restrict__ fuse2_w,
                             const float* __restrict__ fc3_w,
                             const float* __restrict__ fc1_w0,
                             const float* __restrict__ fc2_w0,
                             const float* __restrict__ text) {
    int n = blockIdx.x;     // 0..255
    int k = threadIdx.x;    // 0..255
    int seg = blockIdx.y;   // 0..12
    const float* src;
    __half* dst;
    switch (seg) {
        case 0:  src = fuse1_w + 256 * 256; dst = g_Wh1;              break;
        case 1:  src = fc1_w0 + 512 * 256;  dst = g_Wh1 + 256 * 256;  break;
        case 2:  src = fuse2_w + 256 * 256; dst = g_Wh2;              break;
        case 3:  src = fc2_w0 + 512 * 256;  dst = g_Wh2 + 256 * 256;  break;
        case 4:  src = fc1_w0;              dst = g_WhP;              break;
        case 5:  src = fc1_w0 + 256 * 256;  dst = g_WhP + 256 * 256;  break;
        case 6:  src = fc2_w0;              dst = g_WhP + 512 * 256;  break;
        case 7:  src = fc2_w0 + 256 * 256;  dst = g_WhP + 768 * 256;  break;
        case 8:  src = fuse1_w;             dst = g_WhP + 1024 * 256; break;
        case 9:  src = fuse2_w;             dst = g_WhP + 1280 * 256; break;
        case 10: src = weight;              dst = g_Whw;              break;
        case 11: // fc3: K = 512
            g_Wh3[n * 512 + k]       = __float2half(fc3_w[k * 256 + n]);
            g_Wh3[n * 512 + k + 256] = __float2half(fc3_w[(k + 256) * 256 + n]);
            return;
        default: // text conversion
            g_text16[n * 1024 + k]       = __float2half(text[n * 1024 + k]);
            g_text16[n * 1024 + 256 + k] = __float2half(text[n * 1024 + 256 + k]);
            g_text16[n * 1024 + 512 + k] = __float2half(text[n * 1024 + 512 + k]);
            g_text16[n * 1024 + 768 + k] = __float2half(text[n * 1024 + 768 + k]);
            return;
    }
    dst[n * 256 + k] = __float2half(src[k * 256 + n]);
}

// ---------------- fp16 tensor GEMM (small shapes): C = A_h @ Wt^T -------------
#define HSTAGE 5120             // halfs per stage per matrix (128*40)
__global__ __launch_bounds__(256, 2) void hgemm(
    const __half* __restrict__ A, const __half* __restrict__ Wt,
    float* __restrict__ C, __half* __restrict__ Ch,
    int M, int N, int K, int doRelu) {
    __shared__ __half As[2][128][40];
    __shared__ __half Bs[2][128][40];
    const int tid = threadIdx.x;
    const int wid = tid >> 5, lane = tid & 31;
    const int g = lane >> 2, qt = lane & 3;
    const int warp_m = wid & 1, warp_n = wid >> 1;
    const int row0 = blockIdx.y * 128;
    const int col0 = blockIdx.x * 128;

    const uint32_t aAddr = (uint32_t)__cvta_generic_to_shared(&As[0][0][0]);
    const uint32_t bAddr = (uint32_t)__cvta_generic_to_shared(&Bs[0][0][0]);
    const int ldr = tid >> 2;          // 0..63
    const int ldc = (tid & 3) * 8;     // 0,8,16,24

    float acc[4][4][4];
    #pragma unroll
    for (int i = 0; i < 4; i++)
        #pragma unroll
        for (int j = 0; j < 4; j++)
            #pragma unroll
            for (int r = 0; r < 4; r++) acc[i][j][r] = 0.f;

    const int KT = K >> 5;

    #pragma unroll
    for (int i = 0; i < 2; i++) {
        int r = ldr + 64 * i;
        cp16(aAddr + (uint32_t)(r * 40 + ldc) * 2, A + (size_t)(row0 + r) * K + ldc);
        cp16(bAddr + (uint32_t)(r * 40 + ldc) * 2, Wt + (size_t)(col0 + r) * K + ldc);
    }
    asm volatile("cp.async.commit_group;\n");

    for (int kt = 0; kt < KT; kt++) {
        if (kt + 1 < KT) {
            int kk = (kt + 1) << 5;
            uint32_t so = (uint32_t)(((kt + 1) & 1) * HSTAGE * 2);
            #pragma unroll
            for (int i = 0; i < 2; i++) {
                int r = ldr + 64 * i;
                cp16(aAddr + so + (uint32_t)(r * 40 + ldc) * 2,
                     A + (size_t)(row0 + r) * K + kk + ldc);
                cp16(bAddr + so + (uint32_t)(r * 40 + ldc) * 2,
                     Wt + (size_t)(col0 + r) * K + kk + ldc);
            }
            asm volatile("cp.async.commit_group;\n");
            asm volatile("cp.async.wait_group 1;\n");
        } else {
            asm volatile("cp.async.wait_group 0;\n");
        }
        __syncthreads();

        const __half* Ac = &As[kt & 1][0][0];
        const __half* Bc = &Bs[kt & 1][0][0];
        #pragma unroll
        for (int ks = 0; ks < 2; ks++) {
            int ko = ks * 16;
            uint32_t af[4][4], bfr[4][2];
            #pragma unroll
            for (int mt = 0; mt < 4; mt++) {
                int R = warp_m * 64 + mt * 16 + g;
                af[mt][0] = *(const uint32_t*)&Ac[R * 40 + ko + 2 * qt];
                af[mt][1] = *(const uint32_t*)&Ac[(R + 8) * 40 + ko + 2 * qt];
                af[mt][2] = *(const uint32_t*)&Ac[R * 40 + ko + 2 * qt + 8];
                af[mt][3] = *(const uint32_t*)&Ac[(R + 8) * 40 + ko + 2 * qt + 8];
            }
            #pragma unroll
            for (int nt = 0; nt < 4; nt++) {
                int Cc = warp_n * 32 + nt * 8 + g;
                bfr[nt][0] = *(const uint32_t*)&Bc[Cc * 40 + ko + 2 * qt];
                bfr[nt][1] = *(const uint32_t*)&Bc[Cc * 40 + ko + 2 * qt + 8];
            }
            #pragma unroll
            for (int mt = 0; mt < 4; mt++)
                #pragma unroll
                for (int nt = 0; nt < 4; nt++)
                    mma_f16(acc[mt][nt], af[mt], bfr[nt]);
        }
        __syncthreads();
    }

    #pragma unroll
    for (int mt = 0; mt < 4; mt++) {
        int R = row0 + warp_m * 64 + mt * 16 + g;
        #pragma unroll
        for (int nt = 0; nt < 4; nt++) {
            int Cc = col0 + warp_n * 32 + nt * 8 + 2 * qt;
            float c0 = acc[mt][nt][0], c1 = acc[mt][nt][1];
            float c2 = acc[mt][nt][2], c3 = acc[mt][nt][3];
            if (doRelu) {
                c0 = fmaxf(c0, 0.f); c1 = fmaxf(c1, 0.f);
                c2 = fmaxf(c2, 0.f); c3 = fmaxf(c3, 0.f);
            }
            if (C) {
                float2 v0 = {c0, c1}, v1 = {c2, c3};
                *(float2*)(C + (size_t)R * N + Cc) = v0;
                *(float2*)(C + (size_t)(R + 8) * N + Cc) = v1;
            }
            if (Ch) {
                *(__half2*)(Ch + (size_t)R * N + Cc) = __floats2half2_rn(c0, c1);
                *(__half2*)(Ch + (size_t)(R + 8) * N + Cc) = __floats2half2_rn(c2, c3);
            }
        }
    }
}

// ---------------- fp32-A fp16 GEMM (edge projections), 3-stage pipeline -------
#define ASTG 5120               // floats per A stage (128*40)
#define BSTG 5120               // halfs per B stage (128*40)
__global__ __launch_bounds__(256, 2) void hgemm_f32a(
    const float* __restrict__ A, const __half* __restrict__ Wt,
    __half* __restrict__ Ch, int M, int N, int K) {
    extern __shared__ uint32_t sh[];
    float* As = (float*)sh;                    // [3][128][40] fp32
    __half* Bs = (__half*)(sh + 3 * ASTG);     // [3][128][40] fp16
    const int tid = threadIdx.x;
    const int wid = tid >> 5, lane = tid & 31;
    const int g = lane >> 2, qt = lane & 3;
    const int warp_m = wid >> 1;       // 0..3  (32-row slab)
    const int warp_n = wid & 1;        // 0..1  (64-col slab)
    const int row0 = blockIdx.y * 128;
    const int col0 = blockIdx.x * 128;

    const uint32_t aAddr = (uint32_t)__cvta_generic_to_shared(As);
    const uint32_t bAddr = (uint32_t)__cvta_generic_to_shared(Bs);
    const int ldrA = tid >> 3;         // 0..31
    const int ldcA = (tid & 7) * 4;    // floats
    const int ldrB = tid >> 2;         // 0..63
    const int ldcB = (tid & 3) * 8;    // halfs

    float acc[2][8][4];
    #pragma unroll
    for (int i = 0; i < 2; i++)
        #pragma unroll
        for (int j = 0; j < 8; j++)
            #pragma unroll
            for (int r = 0; r < 4; r++) acc[i][j][r] = 0.f;

    const int KT = K >> 5;   // 8

    #pragma unroll
    for (int s = 0; s < 2; s++) {
        int kk = s << 5;
        uint32_t soA = (uint32_t)(s * ASTG * 4);
        uint32_t soB = (uint32_t)(s * BSTG * 2);
        #pragma unroll
        for (int i = 0; i < 4; i++) {
            int r = ldrA + 32 * i;
            cp16(aAddr + soA + (uint32_t)(r * 40 + ldcA) * 4,
                 A + (size_t)(row0 + r) * K + kk + ldcA);
        }
        #pragma unroll
        for (int i = 0; i < 2; i++) {
            int r = ldrB + 64 * i;
            cp16(bAddr + soB + (uint32_t)(r * 40 + ldcB) * 2,
                 Wt + (size_t)(col0 + r) * K + kk + ldcB);
        }
        asm volatile("cp.async.commit_group;\n");
    }

    for (int kt = 0; kt < KT; kt++) {
        if (kt + 2 < KT) {
            int kk = (kt + 2) << 5;
            int st = (kt + 2) % 3;
            uint32_t soA = (uint32_t)(st * ASTG * 4);
            uint32_t soB = (uint32_t)(st * BSTG * 2);
            #pragma unroll
            for (int i = 0; i < 4; i++) {
                int r = ldrA + 32 * i;
                cp16(aAddr + soA + (uint32_t)(r * 40 + ldcA) * 4,
                     A + (size_t)(row0 + r) * K + kk + ldcA);
            }
            #pragma unroll
            for (int i = 0; i < 2; i++) {
                int r = ldrB + 64 * i;
                cp16(bAddr + soB + (uint32_t)(r * 40 + ldcB) * 2,
                     Wt + (size_t)(col0 + r) * K + kk + ldcB);
            }
            asm volatile("cp.async.commit_group;\n");
            asm volatile("cp.async.wait_group 2;\n");
        } else if (kt + 1 < KT) {
            asm volatile("cp.async.wait_group 1;\n");
        } else {
            asm volatile("cp.async.wait_group 0;\n");
        }
        __syncthreads();

        const int st = kt % 3;
        const float* Ac = As + st * ASTG;
        const __half* Bc = Bs + st * BSTG;
        #pragma unroll
        for (int ks = 0; ks < 2; ks++) {
            int ko = ks * 16;
            uint32_t af[2][4], bfr[8][2];
            #pragma unroll
            for (int mt = 0; mt < 2; mt++) {
                int R = warp_m * 32 + mt * 16 + g;
                float2 v0 = *(const float2*)&Ac[R * 40 + ko + 2 * qt];
                float2 v1 = *(const float2*)&Ac[(R + 8) * 40 + ko + 2 * qt];
                float2 v2 = *(const float2*)&Ac[R * 40 + ko + 2 * qt + 8];
                float2 v3 = *(const float2*)&Ac[(R + 8) * 40 + ko + 2 * qt + 8];
                af[mt][0] = pack_h2(v0.x, v0.y);
                af[mt][1] = pack_h2(v1.x, v1.y);
                af[mt][2] = pack_h2(v2.x, v2.y);
                af[mt][3] = pack_h2(v3.x, v3.y);
            }
            #pragma unroll
            for (int nt = 0; nt < 8; nt++) {
                int Cc = warp_n * 64 + nt * 8 + g;
                bfr[nt][0] = *(const uint32_t*)&Bc[Cc * 40 + ko + 2 * qt];
                bfr[nt][1] = *(const uint32_t*)&Bc[Cc * 40 + ko + 2 * qt + 8];
            }
            #pragma unroll
            for (int mt = 0; mt < 2; mt++)
                #pragma unroll
                for (int nt = 0; nt < 8; nt++)
                    mma_f16(acc[mt][nt], af[mt], bfr[nt]);
        }
        __syncthreads();
    }

    #pragma unroll
    for (int mt = 0; mt < 2; mt++) {
        int R = row0 + warp_m * 32 + mt * 16 + g;
        #pragma unroll
        for (int nt = 0; nt < 8; nt++) {
            int Cc = col0 + warp_n * 64 + nt * 8 + 2 * qt;
            *(__half2*)(Ch + (size_t)R * N + Cc) =
                __floats2half2_rn(acc[mt][nt][0], acc[mt][nt][1]);
            *(__half2*)(Ch + (size_t)(R + 8) * N + Cc) =
                __floats2half2_rn(acc[mt][nt][2], acc[mt][nt][3]);
        }
    }
}

// ---------------- fused score + aggregate: one block per (b,i) ----------------
// Phase 1: 8 warps; each warp does one j at a time with lanes 0-15 -> s1,
//          lanes 16-31 -> s2, all loads 8B/16B.
// Phase 2: thread (half, js, q) owns 4 d values, strides j by 2; partials
//          combined via smem.
__global__ __launch_bounds__(256) void scoreagg_kernel(
    const __half* __restrict__ P,
    const float* __restrict__ adj1, const float* __restrict__ adj2,
    const float* __restrict__ fc1_w1, const float* __restrict__ fc2_w1,
    const float* __restrict__ fc1_b1, const float* __restrict__ fc2_b1,
    __half* __restrict__ OC) {
    int bid = blockIdx.x;            // b*N + i
    int b = bid >> 7;
    int tid = threadIdx.x, wid = tid >> 5, lane = tid & 31;
    __shared__ __align__(16) uint32_t PiA[256];   // A1 (128 half2) | A2 (128 half2)
    __shared__ float w1s[128], w2s[128], sred[8];
    __shared__ float4 sacc[256];

    const __half* Pi = P + (size_t)bid * 1536;
    float d1 = 0.f, d2 = 0.f;
    if (tid < 128) {
        PiA[tid]       = *(const uint32_t*)&Pi[2 * tid];         // A1
        PiA[128 + tid] = *(const uint32_t*)&Pi[512 + 2 * tid];   // A2
        d1 = adj1[bid * 128 + tid];
        d2 = adj2[bid * 128 + tid];
    }
    #pragma unroll
    for (int o = 16; o; o >>= 1) {
        d1 += __shfl_xor_sync(0xffffffffu, d1, o);
        d2 += __shfl_xor_sync(0xffffffffu, d2, o);
    }
    if (tid < 128 && lane == 0) { sred[wid] = d1; sred[4 + wid] = d2; }
    __syncthreads();
    float denom1 = sred[0] + sred[1] + sred[2] + sred[3] + 1.0f;
    float denom2 = sred[4] + sred[5] + sred[6] + sred[7] + 1.0f;

    // phase 1
    {
        int grp = lane >> 4;         // 0 -> matrix1, 1 -> matrix2
        int gl = lane & 15;
        const __half* preB = grp ? g_pre2h : g_pre1h;
        const float* adjp = grp ? adj2 : adj1;
        const float4* wv = (const float4*)(grp ? fc2_w1 : fc1_w1);
        float bb = grp ? fc2_b1[0] : fc1_b1[0];
        float* wsp = grp ? w2s : w1s;
        const uint2* Ai = (const uint2*)PiA + grp * 64;
        for (int jj = 0; jj < 16; jj++) {
            int j = wid * 16 + jj;
            const uint2* e = (const uint2*)(preB + ((size_t)bid * 128 + j) * 512 + 256);
            const uint2* Pj = (const uint2*)(P + (size_t)(b * 128 + j) * 1536
                                             + (grp ? 768 : 256));
            float s = 0.f;
            #pragma unroll
            for (int t = 0; t < 4; t++) {
                int q = gl + 16 * t;     // uint2 index, covers d = 4q..4q+3
                uint2 av = Ai[q], pv = Pj[q], ev = e[q];
                float4 w = wv[q];
                float2 a0 = __half22float2(*(__half2*)&av.x);
                float2 a1 = __half22float2(*(__half2*)&av.y);
                float2 p0 = __half22float2(*(__half2*)&pv.x);
                float2 p1 = __half22float2(*(__half2*)&pv.y);
                float2 e0 = __half22float2(*(__half2*)&ev.x);
                float2 e1 = __half22float2(*(__half2*)&ev.y);
                s = fmaf(fmaxf(a0.x + p0.x + e0.x, 0.f), w.x, s);
                s = fmaf(fmaxf(a0.y + p0.y + e0.y, 0.f), w.y, s);
                s = fmaf(fmaxf(a1.x + p1.x + e1.x, 0.f), w.z, s);
                s = fmaf(fmaxf(a1.y + p1.y + e1.y, 0.f), w.w, s);
            }
            #pragma unroll
            for (int o = 8; o; o >>= 1)
                s += __shfl_xor_sync(0xffffffffu, s, o);
            if (gl == 0)
                wsp[j] = adjp[bid * 128 + j] / (1.f + __expf(-(s + bb)));
        }
    }
    __syncthreads();

    // phase 2
    {
        int half_id = tid >> 7;          // 0 -> out1, 1 -> out2
        int js = (tid >> 6) & 1;         // j parity
        int q = tid & 63;                // uint2 index, d = 4q..4q+3
        const uint2* U = (const uint2*)(P + (size_t)(b * 128) * 1536
                                        + (half_id ? 1280 : 1024));
        const uint2* E = (const uint2*)((half_id ? g_pre2h : g_pre1h)
                                        + (size_t)bid * 128 * 512);
        const float* ws = half_id ? w2s : w1s;
        float4 acc = {0.f, 0.f, 0.f, 0.f};
        #pragma unroll 4
        for (int j = js; j < 128; j += 2) {
            uint2 uv = U[j * 384 + q];
            uint2 ev = E[j * 128 + q];
            float w = ws[j];
            float2 u0 = __half22float2(*(__half2*)&uv.x);
            float2 u1 = __half22float2(*(__half2*)&uv.y);
            float2 f0 = __half22float2(*(__half2*)&ev.x);
            float2 f1 = __half22float2(*(__half2*)&ev.y);
            acc.x = fmaf(w, fmaxf(u0.x + f0.x, 0.f), acc.x);
            acc.y = fmaf(w, fmaxf(u0.y + f0.y, 0.f), acc.y);
            acc.z = fmaf(w, fmaxf(u1.x + f1.x, 0.f), acc.z);
            acc.w = fmaf(w, fmaxf(u1.y + f1.y, 0.f), acc.w);
        }
        sacc[tid] = acc;
        __syncthreads();
        if (js == 0) {
            float4 other = sacc[tid + 64];
            float inv = 1.0f / (half_id ? denom2 : denom1);
            uint2 r;
            r.x = pack_h2((acc.x + other.x) * inv, (acc.y + other.y) * inv);
            r.y = pack_h2((acc.z + other.z) * inv, (acc.w + other.w) * inv);
            *(uint2*)&OC[(size_t)bid * 512 + half_id * 256 + 4 * q] = r;
        }
    }
}

// ---------------- relu + residual + bias + layernorm --------------------------
__global__ __launch_bounds__(256) void ln_kernel(
    const float* __restrict__ H, const float* __restrict__ prev,
    const float* __restrict__ bias, const float* __restrict__ gamma,
    const float* __restrict__ beta, float* __restrict__ dst,
    __half* __restrict__ dst16) {
    int row = blockIdx.x, tid = threadIdx.x;
    float v = fmaxf(H[(size_t)row * 256 + tid], 0.f)
              + prev[(size_t)row * 256 + tid] + bias[tid];
    float mean = blockSum256(v) * (1.0f / 256.0f);
    float c = v - mean;
    float var = blockSum256(c * c) * (1.0f / 256.0f);
    float r = c * rsqrtf(var + 1e-5f) * gamma[tid] + beta[tid];
    dst[(size_t)row * 256 + tid] = r;
    dst16[(size_t)row * 256 + tid] = __float2half(r);
}

// ---------------- self-alignment: outss --------------------------------------
__global__ __launch_bounds__(256) void align_kernel(
    const float* __restrict__ text, const float* __restrict__ textmask,
    const float* __restrict__ AL, const float* __restrict__ abias,
    float* __restrict__ outss) {
    int bid = blockIdx.x;    // b*N + i
    int b = bid >> 7;
    int tid = threadIdx.x;
    __shared__ float xi[256], q[256], lg[128], sred[2];
    xi[tid] = text[(size_t)bid * 256 + tid];
    __syncthreads();
    float acc = 0.f;
    #pragma unroll 4
    for (int k = 0; k < 256; k++) acc = fmaf(xi[k], AL[k * 256 + tid], acc);
    q[tid] = acc;
    __syncthreads();

    int w = tid >> 5, lane = tid & 31;
    for (int j = w * 16; j < w * 16 + 16; j++) {
        const float* tj = text + (size_t)(b * 128 + j) * 256;
        float a = 0.f;
        #pragma unroll
        for (int t = 0; t < 8; t++) {
            int d = lane + 32 * t;
            a = fmaf(q[d], tj[d], a);
        }
        #pragma unroll
        for (int o = 16; o; o >>= 1) a += __shfl_xor_sync(0xffffffffu, a, o);
        if (lane == 0)
            lg[j] = a + (1.0f - textmask[b * 128 + j]) * -1e20f;
    }
    __syncthreads();
    if (tid < 32) {
        float m = -3.4e38f;
        for (int k = tid; k < 128; k += 32) m = fmaxf(m, lg[k]);
        #pragma unroll
        for (int o = 16; o; o >>= 1) m = fmaxf(m, __shfl_xor_sync(0xffffffffu, m, o));
        if (tid == 0) sred[0] = m;
    }
    __syncthreads();
    float mx = sred[0];
    if (tid < 128) lg[tid] = __expf(lg[tid] - mx);
    __syncthreads();
    if (tid < 32) {
        float s = 0.f;
        for (int k = tid; k < 128; k += 32) s += lg[k];
        #pragma unroll
        for (int o = 16; o; o >>= 1) s += __shfl_xor_sync(0xffffffffu, s, o);
        if (tid == 0) sred[1] = s;
    }
    __syncthreads();
    float inv = 1.0f / sred[1];
    float a2 = 0.f;
    for (int j = 0; j < 128; j++)
        a2 = fmaf(lg[j], text[(size_t)(b * 128 + j) * 256 + tid], a2);
    outss[(size_t)bid * 256 + tid] = a2 * inv * textmask[bid] + abias[tid];
}

// ---------------- launch ------------------------------------------------------
#define F32A_SMEM 92160   // 3*(128*40*4) + 3*(128*40*2)

extern "C" void kernel_launch(void* const* d_in, const int* in_sizes, int n_in,
                              void* d_out, int out_size) {
    const float* text      = (const float*)d_in[0];
    const float* adj1      = (const float*)d_in[1];
    const float* adj2      = (const float*)d_in[2];
    const float* edge1     = (const float*)d_in[3];
    const float* edge2     = (const float*)d_in[4];
    const float* textmask  = (const float*)d_in[5];
    const float* weight    = (const float*)d_in[6];
    const float* bias      = (const float*)d_in[7];
    const float* gamma     = (const float*)d_in[8];
    const float* beta      = (const float*)d_in[9];
    const float* fuse1_w   = (const float*)d_in[10];
    const float* fuse2_w   = (const float*)d_in[11];
    const float* fc3_w     = (const float*)d_in[12];
    const float* fc1_w0    = (const float*)d_in[13];
    const float* fc1_w1    = (const float*)d_in[14];
    const float* fc1_b1    = (const float*)d_in[15];
    const float* fc2_w0    = (const float*)d_in[16];
    const float* fc2_w1    = (const float*)d_in[17];
    const float* fc2_b1    = (const float*)d_in[18];
    const float* align_lin = (const float*)d_in[19];
    const float* align_bias= (const float*)d_in[20];
    float* out = (float*)d_out;

    static int attr_done = 0;
    if (!attr_done) {
        cudaFuncSetAttribute(hgemm_f32a,
                             cudaFuncAttributeMaxDynamicSharedMemorySize,
                             F32A_SMEM);
        attr_done = 1;
    }

    __half *p_pre1, *p_pre2, *p_Wh1, *p_Wh2, *p_WhP, *p_Wh3,
           *p_Whw, *p_t16, *p_P16, *p_out16, *p_OC16;
    float *p_out, *p_H;
    cudaGetSymbolAddress((void**)&p_pre1,  g_pre1h);
    cudaGetSymbolAddress((void**)&p_pre2,  g_pre2h);
    cudaGetSymbolAddress((void**)&p_Wh1,   g_Wh1);
    cudaGetSymbolAddress((void**)&p_Wh2,   g_Wh2);
    cudaGetSymbolAddress((void**)&p_WhP,   g_WhP);
    cudaGetSymbolAddress((void**)&p_Wh3,   g_Wh3);
    cudaGetSymbolAddress((void**)&p_Whw,   g_Whw);
    cudaGetSymbolAddress((void**)&p_t16,   g_text16);
    cudaGetSymbolAddress((void**)&p_P16,   g_P16);
    cudaGetSymbolAddress((void**)&p_out16, g_out16);
    cudaGetSymbolAddress((void**)&p_OC16,  g_OC16);
    cudaGetSymbolAddress((void**)&p_out,   g_out);
    cudaGetSymbolAddress((void**)&p_H,     g_H);

    // (1) weight repacks + text16 in one launch
    repack_all_h<<<dim3(256, 13), 256>>>(weight, fuse1_w, fuse2_w, fc3_w,
                                         fc1_w0, fc2_w0, text);

    // (2) out = relu(text @ weight), fp32 + fp16
    hgemm<<<dim3(2, 8), 256>>>(p_t16, p_Whw, p_out, p_out16, BN2, 256, 256, 1);

    // (3,4) loop-invariant edge projections, 3-stage pipeline
    hgemm_f32a<<<dim3(4, 1024), 256, F32A_SMEM>>>(edge1, p_Wh1, p_pre1,
                                                  ROWS_E, 512, 256);
    hgemm_f32a<<<dim3(4, 1024), 256, F32A_SMEM>>>(edge2, p_Wh2, p_pre2,
                                                  ROWS_E, 512, 256);

    for (int it = 0; it < 3; it++) {
        // P16 = out @ Wproj
        hgemm<<<dim3(12, 8), 256>>>(p_out16, p_WhP, (float*)0, p_P16,
                                    BN2, 1536, 256, 0);
        scoreagg_kernel<<<BN2, 256>>>(p_P16, adj1, adj2, fc1_w1, fc2_w1,
                                      fc1_b1, fc2_b1, p_OC16);
        // H = [out1|out2] @ fc3_w
        hgemm<<<dim3(2, 8), 256>>>(p_OC16, p_Wh3, p_H, (__half*)0,
                                   BN2, 256, 512, 0);
        float* dst = (it == 2) ? out : p_out;
        ln_kernel<<<BN2, 256>>>(p_H, p_out, bias, gamma, beta, dst, p_out16);
    }

    // independent self-alignment output
    align_kernel<<<BN2, 256>>>(text, textmask, align_lin, align_bias,
                               out + BN2 * 256);
}